// round 12
// baseline (speedup 1.0000x reference)
#include <cuda_runtime.h>
#include <cuda.h>
#include <cuda_bf16.h>
#include <cstdint>
#include <math.h>

// Problem dims (fixed by the dataset)
#define BSZ 16
#define QQ  300
#define NC  81
#define HH  64
#define WWD 64
#define TT  400
#define HM  128
#define PP  (BSZ*QQ)     // 4800
#define HWX (HH*WWD)     // 4096

// ---------------- scratch (device globals; no allocation allowed) -------------
__device__ __align__(1024) __nv_bfloat16 g_A1[(size_t)PP*HWX];   // logits bf16
__device__ __align__(1024) __nv_bfloat16 g_A2[(size_t)PP*HWX];   // sigmoid bf16
__device__ __align__(1024) __nv_bfloat16 g_tm[(size_t)TT*HWX];   // resized targets bf16
__device__ float g_tsum[TT];
__device__ float g_snp[PP];     // sum log_sigmoid(-m)
__device__ float g_psum[PP];    // sum sigmoid(m)
__device__ float g_prob[(size_t)PP*NC];
__device__ int   g_lab[TT];     // decoded labels

// ---------------- small helpers -----------------------------------------------
__device__ __forceinline__ float block_reduce_sum(float v, float* sh) {
    int lane = threadIdx.x & 31, w = threadIdx.x >> 5;
#pragma unroll
    for (int o = 16; o; o >>= 1) v += __shfl_down_sync(0xffffffffu, v, o);
    if (lane == 0) sh[w] = v;
    __syncthreads();
    if (w == 0) {
        v = (lane < 8) ? sh[lane] : 0.f;
#pragma unroll
        for (int o = 4; o; o >>= 1) v += __shfl_down_sync(0xffffffffu, v, o);
    }
    return v;  // valid on thread 0
}

__device__ __forceinline__ void taps64(int i, int& j0, float w[4]) {
    if (i == 0)       { j0 = 0;   w[0] = 3.f/7.f; w[1] = 3.f/7.f; w[2] = 1.f/7.f; w[3] = 0.f; }
    else if (i == 63) { j0 = 124; w[0] = 0.f;     w[1] = 1.f/7.f; w[2] = 3.f/7.f; w[3] = 3.f/7.f; }
    else              { j0 = 2*i - 1; w[0] = 0.125f; w[1] = 0.375f; w[2] = 0.375f; w[3] = 0.125f; }
}

__device__ __forceinline__ uint32_t smem_u32(const void* p) {
    uint32_t a;
    asm("{ .reg .u64 t; cvta.to.shared.u64 t, %1; cvt.u32.u64 %0, t; }" : "=r"(a) : "l"(p));
    return a;
}

#define SW128(off) ((off) ^ (((off) >> 3) & 0x70))

__device__ __forceinline__ void cpa16(void* dst, const void* src, bool v) {
    uint32_t d = (uint32_t)__cvta_generic_to_shared(dst);
    int n = v ? 16 : 0;
    asm volatile("cp.async.cg.shared.global [%0], [%1], 16, %2;\n" :: "r"(d), "l"(src), "r"(n));
}
__device__ __forceinline__ void cpcommit() { asm volatile("cp.async.commit_group;\n"); }

__device__ __forceinline__ void mma16816(float c[4], const uint32_t a[4], const uint32_t b[2]) {
    asm volatile(
        "mma.sync.aligned.m16n8k16.row.col.f32.bf16.bf16.f32 "
        "{%0,%1,%2,%3}, {%4,%5,%6,%7}, {%8,%9}, {%0,%1,%2,%3};\n"
        : "+f"(c[0]), "+f"(c[1]), "+f"(c[2]), "+f"(c[3])
        : "r"(a[0]), "r"(a[1]), "r"(a[2]), "r"(a[3]), "r"(b[0]), "r"(b[1]));
}

__device__ __forceinline__ void ldsm_x4(uint32_t r[4], uint32_t addr) {
    asm volatile("ldmatrix.sync.aligned.m8n8.x4.shared.b16 {%0,%1,%2,%3}, [%4];"
        : "=r"(r[0]), "=r"(r[1]), "=r"(r[2]), "=r"(r[3]) : "r"(addr));
}

#define MBARRIER_INIT(addr, cnt) \
    asm volatile("mbarrier.init.shared.b64 [%0], %1;" :: "r"((uint32_t)(addr)), "r"((uint32_t)(cnt)) : "memory")

#define MBARRIER_EXPECT_TX(addr, tx) \
    asm volatile("mbarrier.arrive.expect_tx.shared.b64 _, [%0], %1;" :: "r"((uint32_t)(addr)), "r"((uint32_t)(tx)) : "memory")

#define MBARRIER_WAIT_PARITY(mbar_smem_addr, phase_parity) do { \
    uint32_t _mbar = (uint32_t)(mbar_smem_addr); \
    uint32_t _parity = (uint32_t)(phase_parity); \
    uint32_t _done; \
    asm volatile( \
        "{\n\t.reg .pred p;\n\t" \
        "mbarrier.try_wait.parity.acquire.cta.shared::cta.b64 p, [%1], %2;\n\t" \
        "selp.b32 %0, 1, 0, p;\n\t}" \
        : "=r"(_done) : "r"(_mbar), "r"(_parity) : "memory"); \
    if (!_done) { \
        asm volatile( \
            "{\n\t.reg .pred P1;\n\t" \
            "WAIT_LOOP_%=:\n\t" \
            "mbarrier.try_wait.parity.acquire.cta.shared::cta.b64 P1, [%0], %1, 0x989680;\n\t" \
            "@P1 bra.uni WAIT_DONE_%=;\n\t" \
            "bra.uni WAIT_LOOP_%=;\n\t" \
            "WAIT_DONE_%=:\n\t}" \
            :: "r"(_mbar), "r"(_parity) : "memory"); \
    } \
} while (0)

__device__ __forceinline__ void tma2d(uint32_t dst, const CUtensorMap* tmap,
                                      int x, int y, uint32_t mbar) {
    asm volatile(
        "cp.async.bulk.tensor.2d.shared::cta.global.tile.mbarrier::complete_tx::bytes "
        "[%0], [%1, {%2, %3}], [%4];"
        :: "r"(dst), "l"(tmap), "r"(x), "r"(y), "r"(mbar) : "memory");
}

// ---------------- fused aux kernel (label + resize + prep + prob) -------------
__global__ void __launch_bounds__(256) aux_kernel(
    const float* __restrict__ logits, const float* __restrict__ masks,
    const float* __restrict__ tmasks, const void* __restrict__ labels) {
    __shared__ __align__(16) char smr[HM * HH * 4];   // 32KB, branch-dependent use
    int bid = blockIdx.x, tid = threadIdx.x;

    if (bid < PP) {
        int p = bid;
        const float4* src = (const float4*)(masks + (size_t)p * HWX);
        __nv_bfloat162* d1 = (__nv_bfloat162*)(g_A1 + (size_t)p * HWX);
        __nv_bfloat162* d2 = (__nv_bfloat162*)(g_A2 + (size_t)p * HWX);
        float accn = 0.f, accs = 0.f;
        for (int i = tid; i < HWX / 4; i += 256) {
            float4 v = src[i];
            float m[4] = {v.x, v.y, v.z, v.w};
            float s[4];
#pragma unroll
            for (int j = 0; j < 4; ++j) {
                float e = __expf(-fabsf(m[j]));
                float l = __logf(1.f + e);
                s[j] = (m[j] >= 0.f) ? __fdividef(1.f, 1.f + e)
                                     : __fdividef(e, 1.f + e);
                accn -= (fmaxf(m[j], 0.f) + l);
                accs += s[j];
            }
            __nv_bfloat162 a, b;
            a.x = __float2bfloat16(m[0]); a.y = __float2bfloat16(m[1]);
            b.x = __float2bfloat16(m[2]); b.y = __float2bfloat16(m[3]);
            d1[2*i] = a; d1[2*i + 1] = b;
            a.x = __float2bfloat16(s[0]); a.y = __float2bfloat16(s[1]);
            b.x = __float2bfloat16(s[2]); b.y = __float2bfloat16(s[3]);
            d2[2*i] = a; d2[2*i + 1] = b;
        }
        float* shred = (float*)smr;
        float tn = block_reduce_sum(accn, shred);
        __syncthreads();
        float ts = block_reduce_sum(accs, shred);
        if (tid == 0) { g_snp[p] = tn; g_psum[p] = ts; }
    } else if (bid < PP + TT) {
        int t = bid - PP;
        const float* src = tmasks + (size_t)t * HM * HM;
        float (*htmp)[HH] = (float(*)[HH])smr;
        for (int e = tid; e < HM * HH; e += 256) {
            int r = e >> 6, i = e & 63;
            int j0; float w[4]; taps64(i, j0, w);
            const float* row = src + r * HM;
            htmp[r][i] = w[0]*row[j0] + w[1]*row[j0+1] + w[2]*row[j0+2] + w[3]*row[j0+3];
        }
        __syncthreads();
        float lsum = 0.f;
        for (int e = tid; e < HWX; e += 256) {
            int o = e >> 6, i = e & 63;
            int j0; float w[4]; taps64(o, j0, w);
            float v = w[0]*htmp[j0][i] + w[1]*htmp[j0+1][i] + w[2]*htmp[j0+2][i] + w[3]*htmp[j0+3][i];
            g_tm[(size_t)t * HWX + e] = __float2bfloat16(v);
            lsum += v;
        }
        __syncthreads();
        __shared__ float shred2[8];
        float tot = block_reduce_sum(lsum, shred2);
        if (tid == 0) g_tsum[t] = tot;
    } else if (bid < PP + TT + PP) {
        int p = bid - PP - TT;
        float* sh = (float*)smr;
        float x = (tid < NC) ? logits[(size_t)p * NC + tid] : -1e30f;
        if (tid < 128) sh[tid] = x;
        __syncthreads();
        for (int s = 64; s > 0; s >>= 1) { if (tid < s) sh[tid] = fmaxf(sh[tid], sh[tid + s]); __syncthreads(); }
        float mx = sh[0]; __syncthreads();
        float e = (tid < NC) ? __expf(x - mx) : 0.f;
        if (tid < 128) sh[tid] = e;
        __syncthreads();
        for (int s = 64; s > 0; s >>= 1) { if (tid < s) sh[tid] += sh[tid + s]; __syncthreads(); }
        float inv = __fdividef(1.f, sh[0]);
        if (tid < NC) g_prob[(size_t)p * NC + tid] = e * inv;
    } else {
        __shared__ int odd_nz;
        if (tid == 0) odd_nz = 0;
        __syncthreads();
        const int* li = (const int*)labels;
        for (int i = tid; i < TT / 2; i += 256)
            if (li[2 * i + 1] != 0) atomicOr(&odd_nz, 1);
        __syncthreads();
        bool is64 = (odd_nz == 0);
        for (int t = tid; t < TT; t += 256)
            g_lab[t] = is64 ? (int)((const long long*)labels)[t] : li[t];
    }
}

// ---------------- shared epilogue pieces --------------------------------------
struct TInfo {
    float cx, cy, w, h, x0, y0, x1, y1, area, tsum;
    int lab, pad;
};

__device__ __forceinline__ void fill_tinfo(TInfo* sT, int n0, const float* tboxes, int tid) {
    if (tid < 128) {
        int t = n0 + tid;
        TInfo ti;
        if (t < TT) {
            float4 tb = *(const float4*)(tboxes + 4 * t);
            ti.cx = tb.x; ti.cy = tb.y; ti.w = tb.z; ti.h = tb.w;
            ti.x0 = tb.x - 0.5f * tb.z; ti.y0 = tb.y - 0.5f * tb.w;
            ti.x1 = tb.x + 0.5f * tb.z; ti.y1 = tb.y + 0.5f * tb.w;
            ti.area = tb.z * tb.w;
            ti.tsum = g_tsum[t];
            ti.lab = g_lab[t];
        } else {
            ti.cx = ti.cy = ti.w = ti.h = 0.f;
            ti.x0 = ti.y0 = ti.x1 = ti.y1 = 0.f;
            ti.area = ti.tsum = 0.f; ti.lab = 0;
        }
        ti.pad = 0;
        sT[tid] = ti;
    }
}

// compute one output pair from the two accumulator fragments
__device__ __forceinline__ float cost_elem(
    float d1, float d2, const TInfo& ti, const float4& pb,
    float px0, float py0, float px1, float py1, float parea,
    float snp_p, float psum_p, const float* prow) {
    const float inv_hw = 1.0f / (float)HWX;
    float l1 = fabsf(pb.x - ti.cx) + fabsf(pb.y - ti.cy)
             + fabsf(pb.z - ti.w) + fabsf(pb.w - ti.h);
    float ix0 = fmaxf(px0, ti.x0), iy0 = fmaxf(py0, ti.y0);
    float ix1 = fminf(px1, ti.x1), iy1 = fminf(py1, ti.y1);
    float inter = fmaxf(ix1 - ix0, 0.f) * fmaxf(iy1 - iy0, 0.f);
    float uni = parea + ti.area - inter;
    float iou = inter / uni;
    float ex0 = fminf(px0, ti.x0), ey0 = fminf(py0, ti.y0);
    float ex1 = fmaxf(px1, ti.x1), ey1 = fmaxf(py1, ti.y1);
    float enc = fmaxf(ex1 - ex0, 0.f) * fmaxf(ey1 - ey0, 0.f);
    float giou = iou - (enc - uni) / enc;
    float cmask = -(d1 + snp_p) * inv_hw;
    float cdice = 1.f - (2.f * d2 + 1e-5f) / (psum_p + ti.tsum + 1e-5f);
    float ccls = -prow[ti.lab];
    return 5.f * l1 - 2.f * giou + 2.f * ccls + 5.f * cmask + 5.f * cdice;
}

// ---------------- GEMM path A: TMA + mma.sync, 8 warps, frag double-buffer ----
#define BM 128
#define BN 128
#define BKS 64                 // K elems per stage (128B rows -> SW128)
#define KTN (HWX / BKS)        // 64 stages
#define NSTG 4
#define MATB (128 * 128)       // 16KB per mat tile
#define STGB (3 * MATB)        // 48KB per stage
#define NT_TMA 256
#define DYN_SMEM (NSTG * STGB + 1024)

__global__ void __launch_bounds__(NT_TMA, 1) gemm_tma(
    const __grid_constant__ CUtensorMap tmA1,
    const __grid_constant__ CUtensorMap tmA2,
    const __grid_constant__ CUtensorMap tmB,
    const float* __restrict__ pboxes, const float* __restrict__ tboxes,
    float* __restrict__ out) {
    extern __shared__ char dsm[];
    __shared__ TInfo sT[128];
    __shared__ __align__(8) unsigned long long smbar[NSTG];

    uint32_t dbase = (smem_u32(dsm) + 1023) & ~1023u;
    uint32_t mb = smem_u32(smbar);

    int tid = threadIdx.x, lane = tid & 31, warp = tid >> 5;
    int n0 = blockIdx.x * BN, m0 = blockIdx.y * BM;
    int nvalid = min(BN, TT - n0);
    int wr = (warp & 3) * 32;    // 4 warps along M (32 rows each)
    int wc = (warp >> 2) * 64;   // 2 warps along N (64 cols each)

    if (tid == 0)
        for (int s = 0; s < NSTG; ++s) MBARRIER_INIT(mb + 8 * s, 1);
    fill_tinfo(sT, n0, tboxes, tid);
    __syncthreads();

    if (tid == 0) {
#pragma unroll
        for (int s = 0; s < 3; ++s) {
            uint32_t fb = mb + 8 * s;
            MBARRIER_EXPECT_TX(fb, STGB);
            uint32_t d = dbase + s * STGB;
            int x = s * BKS;
            tma2d(d,            &tmA1, x, m0, fb);
            tma2d(d + MATB,     &tmA2, x, m0, fb);
            tma2d(d + 2 * MATB, &tmB,  x, n0, fb);
        }
    }

    float acc[2][2][8][4];   // [mat][mi][ni][frag], warp tile 32x64
#pragma unroll
    for (int a = 0; a < 2; ++a)
#pragma unroll
        for (int b = 0; b < 2; ++b)
#pragma unroll
            for (int c = 0; c < 8; ++c)
#pragma unroll
                for (int d = 0; d < 4; ++d) acc[a][b][c][d] = 0.f;

    int a_row_l = (lane & 15);
    int a_coff  = (lane >> 4) * 16;          // bytes
    int b_row_l = (lane & 7) + ((lane >> 4) * 8);
    int b_coff  = ((lane >> 3) & 1) * 16;    // bytes

    uint32_t phases = 0;

    // double-buffered fragments
    uint32_t afb[2][2][2][4];   // [buf][mat][mi][4]
    uint32_t bfb[2][8][2];      // [buf][ni][2]

    auto loadFrags = [&](uint32_t sb, int ks, uint32_t af[2][2][4], uint32_t bf[8][2]) {
        int cbyte = ks * 32;
#pragma unroll
        for (int mi = 0; mi < 2; ++mi) {
            uint32_t off = (uint32_t)((wr + mi * 16 + a_row_l) * 128 + cbyte + a_coff);
            uint32_t sw = SW128(off);
            ldsm_x4(af[0][mi], sb + sw);
            ldsm_x4(af[1][mi], sb + MATB + sw);
        }
#pragma unroll
        for (int nh = 0; nh < 4; ++nh) {
            uint32_t regs[4];
            uint32_t off = (uint32_t)((wc + nh * 16 + b_row_l) * 128 + cbyte + b_coff);
            ldsm_x4(regs, sb + 2 * MATB + SW128(off));
            bf[nh * 2][0] = regs[0]; bf[nh * 2][1] = regs[1];
            bf[nh * 2 + 1][0] = regs[2]; bf[nh * 2 + 1][1] = regs[3];
        }
    };

    for (int kt = 0; kt < KTN; ++kt) {
        __syncthreads();   // all warps done reading slot (kt-1)&3
        if (tid == 0 && kt + 3 < KTN) {
            int sl = (kt + 3) & 3;
            uint32_t fb = mb + 8 * sl;
            MBARRIER_EXPECT_TX(fb, STGB);
            uint32_t d = dbase + sl * STGB;
            int x = (kt + 3) * BKS;
            tma2d(d,            &tmA1, x, m0, fb);
            tma2d(d + MATB,     &tmA2, x, m0, fb);
            tma2d(d + 2 * MATB, &tmB,  x, n0, fb);
        }
        int sl = kt & 3;
        MBARRIER_WAIT_PARITY(mb + 8 * sl, (phases >> sl) & 1);
        phases ^= 1u << sl;

        uint32_t sb = dbase + sl * STGB;
        loadFrags(sb, 0, afb[0], bfb[0]);
#pragma unroll
        for (int ks = 0; ks < 4; ++ks) {
            int cur = ks & 1;
            if (ks < 3) loadFrags(sb, ks + 1, afb[cur ^ 1], bfb[cur ^ 1]);
#pragma unroll
            for (int s2 = 0; s2 < 2; ++s2)
#pragma unroll
                for (int mi = 0; mi < 2; ++mi)
#pragma unroll
                    for (int ni = 0; ni < 8; ++ni)
                        mma16816(acc[s2][mi][ni], afb[cur][s2][mi], bfb[cur][ni]);
        }
    }

    // ---- fused cost epilogue (warp tile 32x64) ----
#pragma unroll
    for (int mi = 0; mi < 2; ++mi) {
#pragma unroll
        for (int rh = 0; rh < 2; ++rh) {
            int p = m0 + wr + mi * 16 + (lane >> 2) + rh * 8;
            if (p >= PP) continue;
            float snp_p = g_snp[p], psum_p = g_psum[p];
            float4 pb = *(const float4*)(pboxes + 4 * p);
            float px0 = pb.x - 0.5f * pb.z, py0 = pb.y - 0.5f * pb.w;
            float px1 = pb.x + 0.5f * pb.z, py1 = pb.y + 0.5f * pb.w;
            float parea = pb.z * pb.w;
            const float* prow = g_prob + (size_t)p * NC;
#pragma unroll
            for (int ni = 0; ni < 8; ++ni) {
                int tl0 = wc + ni * 8 + 2 * (lane & 3);
                if (tl0 >= nvalid) continue;
                float r2[2];
#pragma unroll
                for (int cc = 0; cc < 2; ++cc)
                    r2[cc] = cost_elem(acc[0][mi][ni][rh * 2 + cc], acc[1][mi][ni][rh * 2 + cc],
                                       sT[tl0 + cc], pb, px0, py0, px1, py1, parea,
                                       snp_p, psum_p, prow);
                *(float2*)(out + (size_t)p * TT + n0 + tl0) = make_float2(r2[0], r2[1]);
            }
        }
    }
}

// ---------------- GEMM path B: cp.async fallback (proven) ---------------------
#define BK 32
#define SAK 40
#define STAGES 4
#define KT_N (HWX / BK)
#define NT_FB 512
#define STAGE_ELEMS (3 * BM * SAK)
#define SMEM_BYTES_FB (STAGES * STAGE_ELEMS * 2 + 128 * (int)sizeof(TInfo))

__global__ void __launch_bounds__(NT_FB, 1) gemm_cpasync(
    const float* __restrict__ pboxes, const float* __restrict__ tboxes,
    float* __restrict__ out) {
    extern __shared__ __align__(16) char smem_raw[];
    __nv_bfloat16* sBuf = (__nv_bfloat16*)smem_raw;
    TInfo* sT = (TInfo*)(smem_raw + STAGES * STAGE_ELEMS * 2);

    int tid = threadIdx.x, lane = tid & 31, warp = tid >> 5;
    int n0 = blockIdx.x * BN, m0 = blockIdx.y * BM;
    int nvalid = min(BN, TT - n0);
    int wr = (warp & 3) * 32;
    int wc = (warp >> 2) * 32;

    fill_tinfo(sT, n0, tboxes, tid);

    float acc[2][2][4][4];
#pragma unroll
    for (int a = 0; a < 2; ++a)
#pragma unroll
        for (int b = 0; b < 2; ++b)
#pragma unroll
            for (int c = 0; c < 4; ++c)
#pragma unroll
                for (int d = 0; d < 4; ++d) acc[a][b][c][d] = 0.f;

    int a_row_l = (lane & 15);
    int a_col_l = (lane >> 4) * 8;
    int b_row_l = (lane & 7) + ((lane >> 4) * 8);
    int b_col_l = ((lane >> 3) & 1) * 8;

    auto loadStage = [&](int slot, int kt) {
        __nv_bfloat16* base = sBuf + slot * STAGE_ELEMS;
        int k0 = kt * BK;
#pragma unroll
        for (int it = 0; it < 3; ++it) {
            int i = tid + it * NT_FB;
            int mat = i >> 9;
            int rem = i & 511;
            int row = rem >> 2;
            int ch  = rem & 3;
            __nv_bfloat16* dst = base + mat * BM * SAK + row * SAK + ch * 8;
            const __nv_bfloat16* src;
            bool v;
            if (mat < 2) {
                int p = m0 + row;
                v = p < PP;
                const __nv_bfloat16* g = (mat == 0) ? g_A1 : g_A2;
                src = g + ((size_t)(v ? p : 0) * HWX + k0 + ch * 8);
            } else {
                int t = n0 + row;
                v = t < TT;
                src = g_tm + ((size_t)(v ? t : 0) * HWX + k0 + ch * 8);
            }
            cpa16(dst, src, v);
        }
        cpcommit();
    };

    loadStage(0, 0);
    loadStage(1, 1);
    loadStage(2, 2);

    for (int kt = 0; kt < KT_N; ++kt) {
        asm volatile("cp.async.wait_group 2;" ::: "memory");
        __syncthreads();
        int kl = kt + STAGES - 1;
        if (kl < KT_N) loadStage(kl & 3, kl);

        const __nv_bfloat16* S = sBuf + (kt & 3) * STAGE_ELEMS;
        uint32_t sbA1 = (uint32_t)__cvta_generic_to_shared(S);
        uint32_t sbA2 = sbA1 + BM * SAK * 2;
        uint32_t sbB  = sbA1 + 2 * BM * SAK * 2;
#pragma unroll
        for (int ks = 0; ks < 2; ++ks) {
            int cb = ks * 16;
            uint32_t af[2][2][4];
#pragma unroll
            for (int mi = 0; mi < 2; ++mi) {
                uint32_t ra = ((wr + mi * 16 + a_row_l) * SAK + cb + a_col_l) * 2;
                ldsm_x4(af[0][mi], sbA1 + ra);
                ldsm_x4(af[1][mi], sbA2 + ra);
            }
            uint32_t bf[4][2];
#pragma unroll
            for (int nh = 0; nh < 2; ++nh) {
                uint32_t regs[4];
                uint32_t rb = ((wc + nh * 16 + b_row_l) * SAK + cb + b_col_l) * 2;
                ldsm_x4(regs, sbB + rb);
                bf[nh * 2][0] = regs[0]; bf[nh * 2][1] = regs[1];
                bf[nh * 2 + 1][0] = regs[2]; bf[nh * 2 + 1][1] = regs[3];
            }
#pragma unroll
            for (int s2 = 0; s2 < 2; ++s2)
#pragma unroll
                for (int mi = 0; mi < 2; ++mi)
#pragma unroll
                    for (int ni = 0; ni < 4; ++ni)
                        mma16816(acc[s2][mi][ni], af[s2][mi], bf[ni]);
        }
    }

#pragma unroll
    for (int mi = 0; mi < 2; ++mi) {
#pragma unroll
        for (int rh = 0; rh < 2; ++rh) {
            int p = m0 + wr + mi * 16 + (lane >> 2) + rh * 8;
            if (p >= PP) continue;
            float snp_p = g_snp[p], psum_p = g_psum[p];
            float4 pb = *(const float4*)(pboxes + 4 * p);
            float px0 = pb.x - 0.5f * pb.z, py0 = pb.y - 0.5f * pb.w;
            float px1 = pb.x + 0.5f * pb.z, py1 = pb.y + 0.5f * pb.w;
            float parea = pb.z * pb.w;
            const float* prow = g_prob + (size_t)p * NC;
#pragma unroll
            for (int ni = 0; ni < 4; ++ni) {
                int tl0 = wc + ni * 8 + 2 * (lane & 3);
                if (tl0 >= nvalid) continue;
                float r2[2];
#pragma unroll
                for (int cc = 0; cc < 2; ++cc)
                    r2[cc] = cost_elem(acc[0][mi][ni][rh * 2 + cc], acc[1][mi][ni][rh * 2 + cc],
                                       sT[tl0 + cc], pb, px0, py0, px1, py1, parea,
                                       snp_p, psum_p, prow);
                *(float2*)(out + (size_t)p * TT + n0 + tl0) = make_float2(r2[0], r2[1]);
            }
        }
    }
}

// ---------------- host: tensormap encoding + launch ---------------------------
typedef CUresult (*PFN_encodeTiled)(
    CUtensorMap*, CUtensorMapDataType, cuuint32_t, void*,
    const cuuint64_t*, const cuuint64_t*, const cuuint32_t*, const cuuint32_t*,
    CUtensorMapInterleave, CUtensorMapSwizzle, CUtensorMapL2promotion,
    CUtensorMapFloatOOBfill);

static CUresult encode_map(PFN_encodeTiled enc, CUtensorMap* tm, void* ptr,
                           unsigned long long rows) {
    cuuint64_t dims[2]    = {(cuuint64_t)HWX, (cuuint64_t)rows};
    cuuint64_t strides[1] = {(cuuint64_t)HWX * 2};
    cuuint32_t box[2]     = {BKS, 128};
    cuuint32_t estr[2]    = {1, 1};
    return enc(tm, CU_TENSOR_MAP_DATA_TYPE_BFLOAT16, 2, ptr, dims, strides, box, estr,
               CU_TENSOR_MAP_INTERLEAVE_NONE, CU_TENSOR_MAP_SWIZZLE_128B,
               CU_TENSOR_MAP_L2_PROMOTION_L2_128B, CU_TENSOR_MAP_FLOAT_OOB_FILL_NONE);
}

extern "C" void kernel_launch(void* const* d_in, const int* in_sizes, int n_in,
                              void* d_out, int out_size) {
    const float* pred_logits = (const float*)d_in[0];
    const float* pred_boxes  = (const float*)d_in[1];
    const float* pred_masks  = (const float*)d_in[2];
    const float* tgt_boxes   = (const float*)d_in[3];
    const float* tgt_masks   = (const float*)d_in[4];
    const void*  tgt_labels  = (const void*)d_in[5];
    float* out = (float*)d_out;

    aux_kernel<<<PP + TT + PP + 1, 256>>>(pred_logits, pred_masks, tgt_masks, tgt_labels);

    // Try the TMA path; verified fallback to the proven cp.async path.
    bool tma_ok = false;
    alignas(64) CUtensorMap tmA1, tmA2, tmB;
    void* fp = nullptr;
#if CUDART_VERSION >= 12000
    cudaDriverEntryPointQueryResult qr;
    cudaError_t e0 = cudaGetDriverEntryPoint("cuTensorMapEncodeTiled", &fp,
                                             cudaEnableDefault, &qr);
#else
    cudaError_t e0 = cudaGetDriverEntryPoint("cuTensorMapEncodeTiled", &fp,
                                             cudaEnableDefault);
#endif
    if (e0 == cudaSuccess && fp != nullptr) {
        PFN_encodeTiled enc = (PFN_encodeTiled)fp;
        void *pa1 = nullptr, *pa2 = nullptr, *pb = nullptr;
        cudaError_t s1 = cudaGetSymbolAddress(&pa1, g_A1);
        cudaError_t s2 = cudaGetSymbolAddress(&pa2, g_A2);
        cudaError_t s3 = cudaGetSymbolAddress(&pb,  g_tm);
        if (s1 == cudaSuccess && s2 == cudaSuccess && s3 == cudaSuccess) {
            CUresult r1 = encode_map(enc, &tmA1, pa1, PP);
            CUresult r2 = encode_map(enc, &tmA2, pa2, PP);
            CUresult r3 = encode_map(enc, &tmB,  pb,  TT);
            tma_ok = (r1 == CUDA_SUCCESS && r2 == CUDA_SUCCESS && r3 == CUDA_SUCCESS);
        }
    }

    dim3 grid((TT + BN - 1) / BN, (PP + BM - 1) / BM);
    if (tma_ok) {
        cudaFuncSetAttribute(gemm_tma, cudaFuncAttributeMaxDynamicSharedMemorySize, DYN_SMEM);
        gemm_tma<<<grid, NT_TMA, DYN_SMEM>>>(tmA1, tmA2, tmB, pred_boxes, tgt_boxes, out);
    } else {
        cudaFuncSetAttribute(gemm_cpasync, cudaFuncAttributeMaxDynamicSharedMemorySize, SMEM_BYTES_FB);
        gemm_cpasync<<<grid, NT_FB, SMEM_BYTES_FB>>>(pred_boxes, tgt_boxes, out);
    }
}

// round 13
// speedup vs baseline: 1.3164x; 1.3164x over previous
#include <cuda_runtime.h>
#include <cuda.h>
#include <cuda_bf16.h>
#include <cstdint>
#include <math.h>

// Problem dims (fixed by the dataset)
#define BSZ 16
#define QQ  300
#define NC  81
#define HH  64
#define WWD 64
#define TT  400
#define HM  128
#define PP  (BSZ*QQ)     // 4800
#define HWX (HH*WWD)     // 4096

// ---------------- scratch (device globals; no allocation allowed) -------------
__device__ __align__(1024) __nv_bfloat16 g_A1[(size_t)PP*HWX];   // logits bf16
__device__ __align__(1024) __nv_bfloat16 g_A2[(size_t)PP*HWX];   // sigmoid bf16
__device__ __align__(1024) __nv_bfloat16 g_tm[(size_t)TT*HWX];   // resized targets bf16
__device__ float g_tsum[TT];
__device__ float g_snp[PP];     // sum log_sigmoid(-m)
__device__ float g_psum[PP];    // sum sigmoid(m)
__device__ float g_prob[(size_t)PP*NC];
__device__ int   g_lab[TT];     // decoded labels

// ---------------- small helpers -----------------------------------------------
__device__ __forceinline__ float block_reduce_sum(float v, float* sh) {
    int lane = threadIdx.x & 31, w = threadIdx.x >> 5;
#pragma unroll
    for (int o = 16; o; o >>= 1) v += __shfl_down_sync(0xffffffffu, v, o);
    if (lane == 0) sh[w] = v;
    __syncthreads();
    if (w == 0) {
        v = (lane < 8) ? sh[lane] : 0.f;
#pragma unroll
        for (int o = 4; o; o >>= 1) v += __shfl_down_sync(0xffffffffu, v, o);
    }
    return v;  // valid on thread 0
}

__device__ __forceinline__ void taps64(int i, int& j0, float w[4]) {
    if (i == 0)       { j0 = 0;   w[0] = 3.f/7.f; w[1] = 3.f/7.f; w[2] = 1.f/7.f; w[3] = 0.f; }
    else if (i == 63) { j0 = 124; w[0] = 0.f;     w[1] = 1.f/7.f; w[2] = 3.f/7.f; w[3] = 3.f/7.f; }
    else              { j0 = 2*i - 1; w[0] = 0.125f; w[1] = 0.375f; w[2] = 0.375f; w[3] = 0.125f; }
}

__device__ __forceinline__ uint32_t smem_u32(const void* p) {
    uint32_t a;
    asm("{ .reg .u64 t; cvta.to.shared.u64 t, %1; cvt.u32.u64 %0, t; }" : "=r"(a) : "l"(p));
    return a;
}

#define SW128(off) ((off) ^ (((off) >> 3) & 0x70))

__device__ __forceinline__ void cpa16(void* dst, const void* src, bool v) {
    uint32_t d = (uint32_t)__cvta_generic_to_shared(dst);
    int n = v ? 16 : 0;
    asm volatile("cp.async.cg.shared.global [%0], [%1], 16, %2;\n" :: "r"(d), "l"(src), "r"(n));
}
__device__ __forceinline__ void cpcommit() { asm volatile("cp.async.commit_group;\n"); }

__device__ __forceinline__ void mma16816(float c[4], const uint32_t a[4], const uint32_t b[2]) {
    asm volatile(
        "mma.sync.aligned.m16n8k16.row.col.f32.bf16.bf16.f32 "
        "{%0,%1,%2,%3}, {%4,%5,%6,%7}, {%8,%9}, {%0,%1,%2,%3};\n"
        : "+f"(c[0]), "+f"(c[1]), "+f"(c[2]), "+f"(c[3])
        : "r"(a[0]), "r"(a[1]), "r"(a[2]), "r"(a[3]), "r"(b[0]), "r"(b[1]));
}

__device__ __forceinline__ void ldsm_x4(uint32_t r[4], uint32_t addr) {
    asm volatile("ldmatrix.sync.aligned.m8n8.x4.shared.b16 {%0,%1,%2,%3}, [%4];"
        : "=r"(r[0]), "=r"(r[1]), "=r"(r[2]), "=r"(r[3]) : "r"(addr));
}

#define MBARRIER_INIT(addr, cnt) \
    asm volatile("mbarrier.init.shared.b64 [%0], %1;" :: "r"((uint32_t)(addr)), "r"((uint32_t)(cnt)) : "memory")

#define MBARRIER_EXPECT_TX(addr, tx) \
    asm volatile("mbarrier.arrive.expect_tx.shared.b64 _, [%0], %1;" :: "r"((uint32_t)(addr)), "r"((uint32_t)(tx)) : "memory")

#define MBARRIER_WAIT_PARITY(mbar_smem_addr, phase_parity) do { \
    uint32_t _mbar = (uint32_t)(mbar_smem_addr); \
    uint32_t _parity = (uint32_t)(phase_parity); \
    uint32_t _done; \
    asm volatile( \
        "{\n\t.reg .pred p;\n\t" \
        "mbarrier.try_wait.parity.acquire.cta.shared::cta.b64 p, [%1], %2;\n\t" \
        "selp.b32 %0, 1, 0, p;\n\t}" \
        : "=r"(_done) : "r"(_mbar), "r"(_parity) : "memory"); \
    if (!_done) { \
        asm volatile( \
            "{\n\t.reg .pred P1;\n\t" \
            "WAIT_LOOP_%=:\n\t" \
            "mbarrier.try_wait.parity.acquire.cta.shared::cta.b64 P1, [%0], %1, 0x989680;\n\t" \
            "@P1 bra.uni WAIT_DONE_%=;\n\t" \
            "bra.uni WAIT_LOOP_%=;\n\t" \
            "WAIT_DONE_%=:\n\t}" \
            :: "r"(_mbar), "r"(_parity) : "memory"); \
    } \
} while (0)

__device__ __forceinline__ void tma2d(uint32_t dst, const CUtensorMap* tmap,
                                      int x, int y, uint32_t mbar) {
    asm volatile(
        "cp.async.bulk.tensor.2d.shared::cta.global.tile.mbarrier::complete_tx::bytes "
        "[%0], [%1, {%2, %3}], [%4];"
        :: "r"(dst), "l"(tmap), "r"(x), "r"(y), "r"(mbar) : "memory");
}

// ---------------- fused aux kernel (label + resize + prep + prob) -------------
__global__ void __launch_bounds__(256) aux_kernel(
    const float* __restrict__ logits, const float* __restrict__ masks,
    const float* __restrict__ tmasks, const void* __restrict__ labels) {
    __shared__ __align__(16) char smr[HM * HH * 4];   // 32KB, branch-dependent use
    int bid = blockIdx.x, tid = threadIdx.x;

    if (bid < PP) {
        int p = bid;
        const float4* src = (const float4*)(masks + (size_t)p * HWX);
        __nv_bfloat162* d1 = (__nv_bfloat162*)(g_A1 + (size_t)p * HWX);
        __nv_bfloat162* d2 = (__nv_bfloat162*)(g_A2 + (size_t)p * HWX);
        float accn = 0.f, accs = 0.f;
        for (int i = tid; i < HWX / 4; i += 256) {
            float4 v = src[i];
            float m[4] = {v.x, v.y, v.z, v.w};
            float s[4];
#pragma unroll
            for (int j = 0; j < 4; ++j) {
                float e = __expf(-fabsf(m[j]));
                float l = __logf(1.f + e);
                s[j] = (m[j] >= 0.f) ? __fdividef(1.f, 1.f + e)
                                     : __fdividef(e, 1.f + e);
                accn -= (fmaxf(m[j], 0.f) + l);
                accs += s[j];
            }
            __nv_bfloat162 a, b;
            a.x = __float2bfloat16(m[0]); a.y = __float2bfloat16(m[1]);
            b.x = __float2bfloat16(m[2]); b.y = __float2bfloat16(m[3]);
            d1[2*i] = a; d1[2*i + 1] = b;
            a.x = __float2bfloat16(s[0]); a.y = __float2bfloat16(s[1]);
            b.x = __float2bfloat16(s[2]); b.y = __float2bfloat16(s[3]);
            d2[2*i] = a; d2[2*i + 1] = b;
        }
        float* shred = (float*)smr;
        float tn = block_reduce_sum(accn, shred);
        __syncthreads();
        float ts = block_reduce_sum(accs, shred);
        if (tid == 0) { g_snp[p] = tn; g_psum[p] = ts; }
    } else if (bid < PP + TT) {
        int t = bid - PP;
        const float* src = tmasks + (size_t)t * HM * HM;
        float (*htmp)[HH] = (float(*)[HH])smr;
        for (int e = tid; e < HM * HH; e += 256) {
            int r = e >> 6, i = e & 63;
            int j0; float w[4]; taps64(i, j0, w);
            const float* row = src + r * HM;
            htmp[r][i] = w[0]*row[j0] + w[1]*row[j0+1] + w[2]*row[j0+2] + w[3]*row[j0+3];
        }
        __syncthreads();
        float lsum = 0.f;
        for (int e = tid; e < HWX; e += 256) {
            int o = e >> 6, i = e & 63;
            int j0; float w[4]; taps64(o, j0, w);
            float v = w[0]*htmp[j0][i] + w[1]*htmp[j0+1][i] + w[2]*htmp[j0+2][i] + w[3]*htmp[j0+3][i];
            g_tm[(size_t)t * HWX + e] = __float2bfloat16(v);
            lsum += v;
        }
        __syncthreads();
        __shared__ float shred2[8];
        float tot = block_reduce_sum(lsum, shred2);
        if (tid == 0) g_tsum[t] = tot;
    } else if (bid < PP + TT + PP) {
        int p = bid - PP - TT;
        float* sh = (float*)smr;
        float x = (tid < NC) ? logits[(size_t)p * NC + tid] : -1e30f;
        if (tid < 128) sh[tid] = x;
        __syncthreads();
        for (int s = 64; s > 0; s >>= 1) { if (tid < s) sh[tid] = fmaxf(sh[tid], sh[tid + s]); __syncthreads(); }
        float mx = sh[0]; __syncthreads();
        float e = (tid < NC) ? __expf(x - mx) : 0.f;
        if (tid < 128) sh[tid] = e;
        __syncthreads();
        for (int s = 64; s > 0; s >>= 1) { if (tid < s) sh[tid] += sh[tid + s]; __syncthreads(); }
        float inv = __fdividef(1.f, sh[0]);
        if (tid < NC) g_prob[(size_t)p * NC + tid] = e * inv;
    } else {
        __shared__ int odd_nz;
        if (tid == 0) odd_nz = 0;
        __syncthreads();
        const int* li = (const int*)labels;
        for (int i = tid; i < TT / 2; i += 256)
            if (li[2 * i + 1] != 0) atomicOr(&odd_nz, 1);
        __syncthreads();
        bool is64 = (odd_nz == 0);
        for (int t = tid; t < TT; t += 256)
            g_lab[t] = is64 ? (int)((const long long*)labels)[t] : li[t];
    }
}

// ---------------- shared epilogue pieces --------------------------------------
struct TInfo {
    float cx, cy, w, h, x0, y0, x1, y1, area, tsum;
    int lab, pad;
};

__device__ __forceinline__ void fill_tinfo(TInfo* sT, int n0, const float* tboxes,
                                           int tid, int cnt) {
    for (int i = tid; i < cnt; i += blockDim.x) {
        int t = n0 + i;
        TInfo ti;
        if (t < TT) {
            float4 tb = *(const float4*)(tboxes + 4 * t);
            ti.cx = tb.x; ti.cy = tb.y; ti.w = tb.z; ti.h = tb.w;
            ti.x0 = tb.x - 0.5f * tb.z; ti.y0 = tb.y - 0.5f * tb.w;
            ti.x1 = tb.x + 0.5f * tb.z; ti.y1 = tb.y + 0.5f * tb.w;
            ti.area = tb.z * tb.w;
            ti.tsum = g_tsum[t];
            ti.lab = g_lab[t];
        } else {
            ti.cx = ti.cy = ti.w = ti.h = 0.f;
            ti.x0 = ti.y0 = ti.x1 = ti.y1 = 0.f;
            ti.area = ti.tsum = 0.f; ti.lab = 0;
        }
        ti.pad = 0;
        sT[i] = ti;
    }
}

__device__ __forceinline__ float cost_elem(
    float d1, float d2, const TInfo& ti, const float4& pb,
    float px0, float py0, float px1, float py1, float parea,
    float snp_p, float psum_p, const float* prow) {
    const float inv_hw = 1.0f / (float)HWX;
    float l1 = fabsf(pb.x - ti.cx) + fabsf(pb.y - ti.cy)
             + fabsf(pb.z - ti.w) + fabsf(pb.w - ti.h);
    float ix0 = fmaxf(px0, ti.x0), iy0 = fmaxf(py0, ti.y0);
    float ix1 = fminf(px1, ti.x1), iy1 = fminf(py1, ti.y1);
    float inter = fmaxf(ix1 - ix0, 0.f) * fmaxf(iy1 - iy0, 0.f);
    float uni = parea + ti.area - inter;
    float iou = inter / uni;
    float ex0 = fminf(px0, ti.x0), ey0 = fminf(py0, ti.y0);
    float ex1 = fmaxf(px1, ti.x1), ey1 = fmaxf(py1, ti.y1);
    float enc = fmaxf(ex1 - ex0, 0.f) * fmaxf(ey1 - ey0, 0.f);
    float giou = iou - (enc - uni) / enc;
    float cmask = -(d1 + snp_p) * inv_hw;
    float cdice = 1.f - (2.f * d2 + 1e-5f) / (psum_p + ti.tsum + 1e-5f);
    float ccls = -prow[ti.lab];
    return 5.f * l1 - 2.f * giou + 2.f * ccls + 5.f * cmask + 5.f * cdice;
}

// ---------------- GEMM path A: TMA, 114 CTAs single wave ----------------------
#define BM 128
#define BN_T 160               // 3 n-tiles x 38 m-tiles = 114 CTAs <= 148 SMs
#define NI 10                  // n8 frags per warp (warp tile 32x80)
#define BKS 64                 // K elems per stage (128B rows -> SW128)
#define KTN (HWX / BKS)        // 64 stages
#define NSTG 4
#define MATBA (128 * 128)      // 16KB A tile (128 rows x 128B)
#define MATBB (BN_T * 128)     // 20KB B tile (160 rows x 128B)
#define STGB (2 * MATBA + MATBB)
#define NT_TMA 256
#define DYN_SMEM (NSTG * STGB + 1024)

__global__ void __launch_bounds__(NT_TMA, 1) gemm_tma(
    const __grid_constant__ CUtensorMap tmA1,
    const __grid_constant__ CUtensorMap tmA2,
    const __grid_constant__ CUtensorMap tmB,
    const float* __restrict__ pboxes, const float* __restrict__ tboxes,
    float* __restrict__ out) {
    extern __shared__ char dsm[];
    __shared__ TInfo sT[BN_T];
    __shared__ __align__(8) unsigned long long smbar[NSTG];

    uint32_t dbase = (smem_u32(dsm) + 1023) & ~1023u;
    uint32_t mb = smem_u32(smbar);

    int tid = threadIdx.x, lane = tid & 31, warp = tid >> 5;
    int n0 = blockIdx.x * BN_T, m0 = blockIdx.y * BM;
    int nvalid = min(BN_T, TT - n0);
    int wr = (warp & 3) * 32;       // 4 warps along M (32 rows each)
    int wc = (warp >> 2) * (NI*8);  // 2 warps along N (80 cols each)

    if (tid == 0)
        for (int s = 0; s < NSTG; ++s) MBARRIER_INIT(mb + 8 * s, 1);
    fill_tinfo(sT, n0, tboxes, tid, BN_T);
    __syncthreads();

    if (tid == 0) {
#pragma unroll
        for (int s = 0; s < 3; ++s) {
            uint32_t fb = mb + 8 * s;
            MBARRIER_EXPECT_TX(fb, STGB);
            uint32_t d = dbase + s * STGB;
            int x = s * BKS;
            tma2d(d,             &tmA1, x, m0, fb);
            tma2d(d + MATBA,     &tmA2, x, m0, fb);
            tma2d(d + 2 * MATBA, &tmB,  x, n0, fb);
        }
    }

    float acc[2][2][NI][4];   // [mat][mi][ni][frag], warp tile 32x80
#pragma unroll
    for (int a = 0; a < 2; ++a)
#pragma unroll
        for (int b = 0; b < 2; ++b)
#pragma unroll
            for (int c = 0; c < NI; ++c)
#pragma unroll
                for (int d = 0; d < 4; ++d) acc[a][b][c][d] = 0.f;

    int a_row_l = (lane & 15);
    int a_coff  = (lane >> 4) * 16;          // bytes
    int b_row_l = (lane & 7) + ((lane >> 4) * 8);
    int b_coff  = ((lane >> 3) & 1) * 16;    // bytes

    uint32_t phases = 0;

    for (int kt = 0; kt < KTN; ++kt) {
        __syncthreads();   // all warps done reading slot (kt-1)&3
        if (tid == 0 && kt + 3 < KTN) {
            int sl = (kt + 3) & 3;
            uint32_t fb = mb + 8 * sl;
            MBARRIER_EXPECT_TX(fb, STGB);
            uint32_t d = dbase + sl * STGB;
            int x = (kt + 3) * BKS;
            tma2d(d,             &tmA1, x, m0, fb);
            tma2d(d + MATBA,     &tmA2, x, m0, fb);
            tma2d(d + 2 * MATBA, &tmB,  x, n0, fb);
        }
        int sl = kt & 3;
        MBARRIER_WAIT_PARITY(mb + 8 * sl, (phases >> sl) & 1);
        phases ^= 1u << sl;

        uint32_t sb = dbase + sl * STGB;
#pragma unroll
        for (int ks = 0; ks < 4; ++ks) {
            int cbyte = ks * 32;
            uint32_t af[2][2][4];
#pragma unroll
            for (int mi = 0; mi < 2; ++mi) {
                uint32_t off = (uint32_t)((wr + mi * 16 + a_row_l) * 128 + cbyte + a_coff);
                uint32_t sw = SW128(off);
                ldsm_x4(af[0][mi], sb + sw);
                ldsm_x4(af[1][mi], sb + MATBA + sw);
            }
            uint32_t bf[NI][2];
#pragma unroll
            for (int nh = 0; nh < NI / 2; ++nh) {
                uint32_t regs[4];
                uint32_t off = (uint32_t)((wc + nh * 16 + b_row_l) * 128 + cbyte + b_coff);
                ldsm_x4(regs, sb + 2 * MATBA + SW128(off));
                bf[nh * 2][0] = regs[0]; bf[nh * 2][1] = regs[1];
                bf[nh * 2 + 1][0] = regs[2]; bf[nh * 2 + 1][1] = regs[3];
            }
#pragma unroll
            for (int s2 = 0; s2 < 2; ++s2)
#pragma unroll
                for (int mi = 0; mi < 2; ++mi)
#pragma unroll
                    for (int ni = 0; ni < NI; ++ni)
                        mma16816(acc[s2][mi][ni], af[s2][mi], bf[ni]);
        }
    }

    // ---- fused cost epilogue (warp tile 32x80) ----
#pragma unroll
    for (int mi = 0; mi < 2; ++mi) {
#pragma unroll
        for (int rh = 0; rh < 2; ++rh) {
            int p = m0 + wr + mi * 16 + (lane >> 2) + rh * 8;
            if (p >= PP) continue;
            float snp_p = g_snp[p], psum_p = g_psum[p];
            float4 pb = *(const float4*)(pboxes + 4 * p);
            float px0 = pb.x - 0.5f * pb.z, py0 = pb.y - 0.5f * pb.w;
            float px1 = pb.x + 0.5f * pb.z, py1 = pb.y + 0.5f * pb.w;
            float parea = pb.z * pb.w;
            const float* prow = g_prob + (size_t)p * NC;
#pragma unroll
            for (int ni = 0; ni < NI; ++ni) {
                int tl0 = wc + ni * 8 + 2 * (lane & 3);
                if (tl0 >= nvalid) continue;
                float r2[2];
#pragma unroll
                for (int cc = 0; cc < 2; ++cc)
                    r2[cc] = cost_elem(acc[0][mi][ni][rh * 2 + cc], acc[1][mi][ni][rh * 2 + cc],
                                       sT[tl0 + cc], pb, px0, py0, px1, py1, parea,
                                       snp_p, psum_p, prow);
                *(float2*)(out + (size_t)p * TT + n0 + tl0) = make_float2(r2[0], r2[1]);
            }
        }
    }
}

// ---------------- GEMM path B: cp.async fallback (proven) ---------------------
#define BN_F 128
#define BK 32
#define SAK 40
#define STAGES 4
#define KT_N (HWX / BK)
#define NT_FB 512
#define STAGE_ELEMS (3 * BM * SAK)
#define SMEM_BYTES_FB (STAGES * STAGE_ELEMS * 2 + BN_F * (int)sizeof(TInfo))

__global__ void __launch_bounds__(NT_FB, 1) gemm_cpasync(
    const float* __restrict__ pboxes, const float* __restrict__ tboxes,
    float* __restrict__ out) {
    extern __shared__ __align__(16) char smem_raw[];
    __nv_bfloat16* sBuf = (__nv_bfloat16*)smem_raw;
    TInfo* sT = (TInfo*)(smem_raw + STAGES * STAGE_ELEMS * 2);

    int tid = threadIdx.x, lane = tid & 31, warp = tid >> 5;
    int n0 = blockIdx.x * BN_F, m0 = blockIdx.y * BM;
    int nvalid = min(BN_F, TT - n0);
    int wr = (warp & 3) * 32;
    int wc = (warp >> 2) * 32;

    fill_tinfo(sT, n0, tboxes, tid, BN_F);

    float acc[2][2][4][4];
#pragma unroll
    for (int a = 0; a < 2; ++a)
#pragma unroll
        for (int b = 0; b < 2; ++b)
#pragma unroll
            for (int c = 0; c < 4; ++c)
#pragma unroll
                for (int d = 0; d < 4; ++d) acc[a][b][c][d] = 0.f;

    int a_row_l = (lane & 15);
    int a_col_l = (lane >> 4) * 8;
    int b_row_l = (lane & 7) + ((lane >> 4) * 8);
    int b_col_l = ((lane >> 3) & 1) * 8;

    auto loadStage = [&](int slot, int kt) {
        __nv_bfloat16* base = sBuf + slot * STAGE_ELEMS;
        int k0 = kt * BK;
#pragma unroll
        for (int it = 0; it < 3; ++it) {
            int i = tid + it * NT_FB;
            int mat = i >> 9;
            int rem = i & 511;
            int row = rem >> 2;
            int ch  = rem & 3;
            __nv_bfloat16* dst = base + mat * BM * SAK + row * SAK + ch * 8;
            const __nv_bfloat16* src;
            bool v;
            if (mat < 2) {
                int p = m0 + row;
                v = p < PP;
                const __nv_bfloat16* g = (mat == 0) ? g_A1 : g_A2;
                src = g + ((size_t)(v ? p : 0) * HWX + k0 + ch * 8);
            } else {
                int t = n0 + row;
                v = t < TT;
                src = g_tm + ((size_t)(v ? t : 0) * HWX + k0 + ch * 8);
            }
            cpa16(dst, src, v);
        }
        cpcommit();
    };

    loadStage(0, 0);
    loadStage(1, 1);
    loadStage(2, 2);

    for (int kt = 0; kt < KT_N; ++kt) {
        asm volatile("cp.async.wait_group 2;" ::: "memory");
        __syncthreads();
        int kl = kt + STAGES - 1;
        if (kl < KT_N) loadStage(kl & 3, kl);

        const __nv_bfloat16* S = sBuf + (kt & 3) * STAGE_ELEMS;
        uint32_t sbA1 = (uint32_t)__cvta_generic_to_shared(S);
        uint32_t sbA2 = sbA1 + BM * SAK * 2;
        uint32_t sbB  = sbA1 + 2 * BM * SAK * 2;
#pragma unroll
        for (int ks = 0; ks < 2; ++ks) {
            int cb = ks * 16;
            uint32_t af[2][2][4];
#pragma unroll
            for (int mi = 0; mi < 2; ++mi) {
                uint32_t ra = ((wr + mi * 16 + a_row_l) * SAK + cb + a_col_l) * 2;
                ldsm_x4(af[0][mi], sbA1 + ra);
                ldsm_x4(af[1][mi], sbA2 + ra);
            }
            uint32_t bf[4][2];
#pragma unroll
            for (int nh = 0; nh < 2; ++nh) {
                uint32_t regs[4];
                uint32_t rb = ((wc + nh * 16 + b_row_l) * SAK + cb + b_col_l) * 2;
                ldsm_x4(regs, sbB + rb);
                bf[nh * 2][0] = regs[0]; bf[nh * 2][1] = regs[1];
                bf[nh * 2 + 1][0] = regs[2]; bf[nh * 2 + 1][1] = regs[3];
            }
#pragma unroll
            for (int s2 = 0; s2 < 2; ++s2)
#pragma unroll
                for (int mi = 0; mi < 2; ++mi)
#pragma unroll
                    for (int ni = 0; ni < 4; ++ni)
                        mma16816(acc[s2][mi][ni], af[s2][mi], bf[ni]);
        }
    }

#pragma unroll
    for (int mi = 0; mi < 2; ++mi) {
#pragma unroll
        for (int rh = 0; rh < 2; ++rh) {
            int p = m0 + wr + mi * 16 + (lane >> 2) + rh * 8;
            if (p >= PP) continue;
            float snp_p = g_snp[p], psum_p = g_psum[p];
            float4 pb = *(const float4*)(pboxes + 4 * p);
            float px0 = pb.x - 0.5f * pb.z, py0 = pb.y - 0.5f * pb.w;
            float px1 = pb.x + 0.5f * pb.z, py1 = pb.y + 0.5f * pb.w;
            float parea = pb.z * pb.w;
            const float* prow = g_prob + (size_t)p * NC;
#pragma unroll
            for (int ni = 0; ni < 4; ++ni) {
                int tl0 = wc + ni * 8 + 2 * (lane & 3);
                if (tl0 >= nvalid) continue;
                float r2[2];
#pragma unroll
                for (int cc = 0; cc < 2; ++cc)
                    r2[cc] = cost_elem(acc[0][mi][ni][rh * 2 + cc], acc[1][mi][ni][rh * 2 + cc],
                                       sT[tl0 + cc], pb, px0, py0, px1, py1, parea,
                                       snp_p, psum_p, prow);
                *(float2*)(out + (size_t)p * TT + n0 + tl0) = make_float2(r2[0], r2[1]);
            }
        }
    }
}

// ---------------- host: tensormap encoding + launch ---------------------------
typedef CUresult (*PFN_encodeTiled)(
    CUtensorMap*, CUtensorMapDataType, cuuint32_t, void*,
    const cuuint64_t*, const cuuint64_t*, const cuuint32_t*, const cuuint32_t*,
    CUtensorMapInterleave, CUtensorMapSwizzle, CUtensorMapL2promotion,
    CUtensorMapFloatOOBfill);

static CUresult encode_map(PFN_encodeTiled enc, CUtensorMap* tm, void* ptr,
                           unsigned long long rows, unsigned box_rows) {
    cuuint64_t dims[2]    = {(cuuint64_t)HWX, (cuuint64_t)rows};
    cuuint64_t strides[1] = {(cuuint64_t)HWX * 2};
    cuuint32_t box[2]     = {BKS, box_rows};
    cuuint32_t estr[2]    = {1, 1};
    return enc(tm, CU_TENSOR_MAP_DATA_TYPE_BFLOAT16, 2, ptr, dims, strides, box, estr,
               CU_TENSOR_MAP_INTERLEAVE_NONE, CU_TENSOR_MAP_SWIZZLE_128B,
               CU_TENSOR_MAP_L2_PROMOTION_L2_128B, CU_TENSOR_MAP_FLOAT_OOB_FILL_NONE);
}

extern "C" void kernel_launch(void* const* d_in, const int* in_sizes, int n_in,
                              void* d_out, int out_size) {
    const float* pred_logits = (const float*)d_in[0];
    const float* pred_boxes  = (const float*)d_in[1];
    const float* pred_masks  = (const float*)d_in[2];
    const float* tgt_boxes   = (const float*)d_in[3];
    const float* tgt_masks   = (const float*)d_in[4];
    const void*  tgt_labels  = (const void*)d_in[5];
    float* out = (float*)d_out;

    aux_kernel<<<PP + TT + PP + 1, 256>>>(pred_logits, pred_masks, tgt_masks, tgt_labels);

    // Try the TMA path; verified fallback to the proven cp.async path.
    bool tma_ok = false;
    alignas(64) CUtensorMap tmA1, tmA2, tmB;
    void* fp = nullptr;
#if CUDART_VERSION >= 12000
    cudaDriverEntryPointQueryResult qr;
    cudaError_t e0 = cudaGetDriverEntryPoint("cuTensorMapEncodeTiled", &fp,
                                             cudaEnableDefault, &qr);
#else
    cudaError_t e0 = cudaGetDriverEntryPoint("cuTensorMapEncodeTiled", &fp,
                                             cudaEnableDefault);
#endif
    if (e0 == cudaSuccess && fp != nullptr) {
        PFN_encodeTiled enc = (PFN_encodeTiled)fp;
        void *pa1 = nullptr, *pa2 = nullptr, *pb = nullptr;
        cudaError_t s1 = cudaGetSymbolAddress(&pa1, g_A1);
        cudaError_t s2 = cudaGetSymbolAddress(&pa2, g_A2);
        cudaError_t s3 = cudaGetSymbolAddress(&pb,  g_tm);
        if (s1 == cudaSuccess && s2 == cudaSuccess && s3 == cudaSuccess) {
            CUresult r1 = encode_map(enc, &tmA1, pa1, PP, 128);
            CUresult r2 = encode_map(enc, &tmA2, pa2, PP, 128);
            CUresult r3 = encode_map(enc, &tmB,  pb,  TT, BN_T);
            tma_ok = (r1 == CUDA_SUCCESS && r2 == CUDA_SUCCESS && r3 == CUDA_SUCCESS);
        }
    }

    if (tma_ok) {
        dim3 grid((TT + BN_T - 1) / BN_T, (PP + BM - 1) / BM);   // 3 x 38 = 114
        cudaFuncSetAttribute(gemm_tma, cudaFuncAttributeMaxDynamicSharedMemorySize, DYN_SMEM);
        gemm_tma<<<grid, NT_TMA, DYN_SMEM>>>(tmA1, tmA2, tmB, pred_boxes, tgt_boxes, out);
    } else {
        dim3 grid((TT + BN_F - 1) / BN_F, (PP + BM - 1) / BM);   // 4 x 38 = 152
        cudaFuncSetAttribute(gemm_cpasync, cudaFuncAttributeMaxDynamicSharedMemorySize, SMEM_BYTES_FB);
        gemm_cpasync<<<grid, NT_FB, SMEM_BYTES_FB>>>(pred_boxes, tgt_boxes, out);
    }
}

// round 14
// speedup vs baseline: 1.4507x; 1.1020x over previous
#include <cuda_runtime.h>
#include <cuda.h>
#include <cuda_bf16.h>
#include <cstdint>
#include <math.h>

// Problem dims (fixed by the dataset)
#define BSZ 16
#define QQ  300
#define NC  81
#define HH  64
#define WWD 64
#define TT  400
#define HM  128
#define PP  (BSZ*QQ)     // 4800
#define HWX (HH*WWD)     // 4096

// ---------------- scratch (device globals; no allocation allowed) -------------
__device__ __align__(1024) __nv_bfloat16 g_A1[(size_t)PP*HWX];   // logits bf16
__device__ __align__(1024) __nv_bfloat16 g_A2[(size_t)PP*HWX];   // sigmoid bf16
__device__ __align__(1024) __nv_bfloat16 g_tm[(size_t)TT*HWX];   // resized targets bf16
__device__ float g_tsum[TT];
__device__ float g_snp[PP];     // sum log_sigmoid(-m)
__device__ float g_psum[PP];    // sum sigmoid(m)
__device__ float g_prob[(size_t)PP*NC];
__device__ int   g_lab[TT];     // decoded labels

// ---------------- small helpers -----------------------------------------------
__device__ __forceinline__ float block_reduce_sum(float v, float* sh) {
    int lane = threadIdx.x & 31, w = threadIdx.x >> 5;
#pragma unroll
    for (int o = 16; o; o >>= 1) v += __shfl_down_sync(0xffffffffu, v, o);
    if (lane == 0) sh[w] = v;
    __syncthreads();
    if (w == 0) {
        v = (lane < 8) ? sh[lane] : 0.f;
#pragma unroll
        for (int o = 4; o; o >>= 1) v += __shfl_down_sync(0xffffffffu, v, o);
    }
    return v;  // valid on thread 0
}

__device__ __forceinline__ void taps64(int i, int& j0, float w[4]) {
    if (i == 0)       { j0 = 0;   w[0] = 3.f/7.f; w[1] = 3.f/7.f; w[2] = 1.f/7.f; w[3] = 0.f; }
    else if (i == 63) { j0 = 124; w[0] = 0.f;     w[1] = 1.f/7.f; w[2] = 3.f/7.f; w[3] = 3.f/7.f; }
    else              { j0 = 2*i - 1; w[0] = 0.125f; w[1] = 0.375f; w[2] = 0.375f; w[3] = 0.125f; }
}

__device__ __forceinline__ uint32_t smem_u32(const void* p) {
    uint32_t a;
    asm("{ .reg .u64 t; cvta.to.shared.u64 t, %1; cvt.u32.u64 %0, t; }" : "=r"(a) : "l"(p));
    return a;
}

#define SW128(off) ((off) ^ (((off) >> 3) & 0x70))

__device__ __forceinline__ void cpa16(void* dst, const void* src, bool v) {
    uint32_t d = (uint32_t)__cvta_generic_to_shared(dst);
    int n = v ? 16 : 0;
    asm volatile("cp.async.cg.shared.global [%0], [%1], 16, %2;\n" :: "r"(d), "l"(src), "r"(n));
}
__device__ __forceinline__ void cpcommit() { asm volatile("cp.async.commit_group;\n"); }

__device__ __forceinline__ void mma16816(float c[4], const uint32_t a[4], const uint32_t b[2]) {
    asm volatile(
        "mma.sync.aligned.m16n8k16.row.col.f32.bf16.bf16.f32 "
        "{%0,%1,%2,%3}, {%4,%5,%6,%7}, {%8,%9}, {%0,%1,%2,%3};\n"
        : "+f"(c[0]), "+f"(c[1]), "+f"(c[2]), "+f"(c[3])
        : "r"(a[0]), "r"(a[1]), "r"(a[2]), "r"(a[3]), "r"(b[0]), "r"(b[1]));
}

__device__ __forceinline__ void ldsm_x4(uint32_t r[4], uint32_t addr) {
    asm volatile("ldmatrix.sync.aligned.m8n8.x4.shared.b16 {%0,%1,%2,%3}, [%4];"
        : "=r"(r[0]), "=r"(r[1]), "=r"(r[2]), "=r"(r[3]) : "r"(addr));
}

#define MBARRIER_INIT(addr, cnt) \
    asm volatile("mbarrier.init.shared.b64 [%0], %1;" :: "r"((uint32_t)(addr)), "r"((uint32_t)(cnt)) : "memory")

#define MBARRIER_EXPECT_TX(addr, tx) \
    asm volatile("mbarrier.arrive.expect_tx.shared.b64 _, [%0], %1;" :: "r"((uint32_t)(addr)), "r"((uint32_t)(tx)) : "memory")

#define MBARRIER_WAIT_PARITY(mbar_smem_addr, phase_parity) do { \
    uint32_t _mbar = (uint32_t)(mbar_smem_addr); \
    uint32_t _parity = (uint32_t)(phase_parity); \
    uint32_t _done; \
    asm volatile( \
        "{\n\t.reg .pred p;\n\t" \
        "mbarrier.try_wait.parity.acquire.cta.shared::cta.b64 p, [%1], %2;\n\t" \
        "selp.b32 %0, 1, 0, p;\n\t}" \
        : "=r"(_done) : "r"(_mbar), "r"(_parity) : "memory"); \
    if (!_done) { \
        asm volatile( \
            "{\n\t.reg .pred P1;\n\t" \
            "WAIT_LOOP_%=:\n\t" \
            "mbarrier.try_wait.parity.acquire.cta.shared::cta.b64 P1, [%0], %1, 0x989680;\n\t" \
            "@P1 bra.uni WAIT_DONE_%=;\n\t" \
            "bra.uni WAIT_LOOP_%=;\n\t" \
            "WAIT_DONE_%=:\n\t}" \
            :: "r"(_mbar), "r"(_parity) : "memory"); \
    } \
} while (0)

__device__ __forceinline__ void tma2d(uint32_t dst, const CUtensorMap* tmap,
                                      int x, int y, uint32_t mbar) {
    asm volatile(
        "cp.async.bulk.tensor.2d.shared::cta.global.tile.mbarrier::complete_tx::bytes "
        "[%0], [%1, {%2, %3}], [%4];"
        :: "r"(dst), "l"(tmap), "r"(x), "r"(y), "r"(mbar) : "memory");
}

// ---------------- fused aux kernel (label + resize + prep + prob) -------------
__global__ void __launch_bounds__(256) aux_kernel(
    const float* __restrict__ logits, const float* __restrict__ masks,
    const float* __restrict__ tmasks, const void* __restrict__ labels) {
    __shared__ __align__(16) char smr[HM * HH * 4];   // 32KB, branch-dependent use
    int bid = blockIdx.x, tid = threadIdx.x;

    if (bid < PP) {
        int p = bid;
        const float4* src = (const float4*)(masks + (size_t)p * HWX);
        __nv_bfloat162* d1 = (__nv_bfloat162*)(g_A1 + (size_t)p * HWX);
        __nv_bfloat162* d2 = (__nv_bfloat162*)(g_A2 + (size_t)p * HWX);
        float accn = 0.f, accs = 0.f;
        for (int i = tid; i < HWX / 4; i += 256) {
            float4 v = src[i];
            float m[4] = {v.x, v.y, v.z, v.w};
            float s[4];
#pragma unroll
            for (int j = 0; j < 4; ++j) {
                float e = __expf(-fabsf(m[j]));
                float l = __logf(1.f + e);
                s[j] = (m[j] >= 0.f) ? __fdividef(1.f, 1.f + e)
                                     : __fdividef(e, 1.f + e);
                accn -= (fmaxf(m[j], 0.f) + l);
                accs += s[j];
            }
            __nv_bfloat162 a, b;
            a.x = __float2bfloat16(m[0]); a.y = __float2bfloat16(m[1]);
            b.x = __float2bfloat16(m[2]); b.y = __float2bfloat16(m[3]);
            d1[2*i] = a; d1[2*i + 1] = b;
            a.x = __float2bfloat16(s[0]); a.y = __float2bfloat16(s[1]);
            b.x = __float2bfloat16(s[2]); b.y = __float2bfloat16(s[3]);
            d2[2*i] = a; d2[2*i + 1] = b;
        }
        float* shred = (float*)smr;
        float tn = block_reduce_sum(accn, shred);
        __syncthreads();
        float ts = block_reduce_sum(accs, shred);
        if (tid == 0) { g_snp[p] = tn; g_psum[p] = ts; }
    } else if (bid < PP + TT) {
        int t = bid - PP;
        const float* src = tmasks + (size_t)t * HM * HM;
        float (*htmp)[HH] = (float(*)[HH])smr;
        for (int e = tid; e < HM * HH; e += 256) {
            int r = e >> 6, i = e & 63;
            int j0; float w[4]; taps64(i, j0, w);
            const float* row = src + r * HM;
            htmp[r][i] = w[0]*row[j0] + w[1]*row[j0+1] + w[2]*row[j0+2] + w[3]*row[j0+3];
        }
        __syncthreads();
        float lsum = 0.f;
        for (int e = tid; e < HWX; e += 256) {
            int o = e >> 6, i = e & 63;
            int j0; float w[4]; taps64(o, j0, w);
            float v = w[0]*htmp[j0][i] + w[1]*htmp[j0+1][i] + w[2]*htmp[j0+2][i] + w[3]*htmp[j0+3][i];
            g_tm[(size_t)t * HWX + e] = __float2bfloat16(v);
            lsum += v;
        }
        __syncthreads();
        __shared__ float shred2[8];
        float tot = block_reduce_sum(lsum, shred2);
        if (tid == 0) g_tsum[t] = tot;
    } else if (bid < PP + TT + PP) {
        int p = bid - PP - TT;
        float* sh = (float*)smr;
        float x = (tid < NC) ? logits[(size_t)p * NC + tid] : -1e30f;
        if (tid < 128) sh[tid] = x;
        __syncthreads();
        for (int s = 64; s > 0; s >>= 1) { if (tid < s) sh[tid] = fmaxf(sh[tid], sh[tid + s]); __syncthreads(); }
        float mx = sh[0]; __syncthreads();
        float e = (tid < NC) ? __expf(x - mx) : 0.f;
        if (tid < 128) sh[tid] = e;
        __syncthreads();
        for (int s = 64; s > 0; s >>= 1) { if (tid < s) sh[tid] += sh[tid + s]; __syncthreads(); }
        float inv = __fdividef(1.f, sh[0]);
        if (tid < NC) g_prob[(size_t)p * NC + tid] = e * inv;
    } else {
        __shared__ int odd_nz;
        if (tid == 0) odd_nz = 0;
        __syncthreads();
        const int* li = (const int*)labels;
        for (int i = tid; i < TT / 2; i += 256)
            if (li[2 * i + 1] != 0) atomicOr(&odd_nz, 1);
        __syncthreads();
        bool is64 = (odd_nz == 0);
        for (int t = tid; t < TT; t += 256)
            g_lab[t] = is64 ? (int)((const long long*)labels)[t] : li[t];
    }
}

// ---------------- shared epilogue pieces --------------------------------------
struct TInfo {
    float cx, cy, w, h, x0, y0, x1, y1, area, tsum;
    int lab, pad;
};

__device__ __forceinline__ void fill_tinfo(TInfo* sT, int n0, const float* tboxes,
                                           int tid, int cnt) {
    for (int i = tid; i < cnt; i += blockDim.x) {
        int t = n0 + i;
        TInfo ti;
        if (t < TT) {
            float4 tb = *(const float4*)(tboxes + 4 * t);
            ti.cx = tb.x; ti.cy = tb.y; ti.w = tb.z; ti.h = tb.w;
            ti.x0 = tb.x - 0.5f * tb.z; ti.y0 = tb.y - 0.5f * tb.w;
            ti.x1 = tb.x + 0.5f * tb.z; ti.y1 = tb.y + 0.5f * tb.w;
            ti.area = tb.z * tb.w;
            ti.tsum = g_tsum[t];
            ti.lab = g_lab[t];
        } else {
            ti.cx = ti.cy = ti.w = ti.h = 0.f;
            ti.x0 = ti.y0 = ti.x1 = ti.y1 = 0.f;
            ti.area = ti.tsum = 0.f; ti.lab = 0;
        }
        ti.pad = 0;
        sT[i] = ti;
    }
}

__device__ __forceinline__ float cost_elem(
    float d1, float d2, const TInfo& ti, const float4& pb,
    float px0, float py0, float px1, float py1, float parea,
    float snp_p, float psum_p, const float* prow) {
    const float inv_hw = 1.0f / (float)HWX;
    float l1 = fabsf(pb.x - ti.cx) + fabsf(pb.y - ti.cy)
             + fabsf(pb.z - ti.w) + fabsf(pb.w - ti.h);
    float ix0 = fmaxf(px0, ti.x0), iy0 = fmaxf(py0, ti.y0);
    float ix1 = fminf(px1, ti.x1), iy1 = fminf(py1, ti.y1);
    float inter = fmaxf(ix1 - ix0, 0.f) * fmaxf(iy1 - iy0, 0.f);
    float uni = parea + ti.area - inter;
    float iou = inter / uni;
    float ex0 = fminf(px0, ti.x0), ey0 = fminf(py0, ti.y0);
    float ex1 = fmaxf(px1, ti.x1), ey1 = fmaxf(py1, ti.y1);
    float enc = fmaxf(ex1 - ex0, 0.f) * fmaxf(ey1 - ey0, 0.f);
    float giou = iou - (enc - uni) / enc;
    float cmask = -(d1 + snp_p) * inv_hw;
    float cdice = 1.f - (2.f * d2 + 1e-5f) / (psum_p + ti.tsum + 1e-5f);
    float ccls = -prow[ti.lab];
    return 5.f * l1 - 2.f * giou + 2.f * ccls + 5.f * cmask + 5.f * cdice;
}

// ---------------- GEMM path A: TMA, 129 CTAs single wave, 14 warps -------------
#define BM_T 112               // 43 m-tiles x 3 n-tiles = 129 CTAs <= 148 SMs
#define BN_T 160
#define NI 10                  // n8 frags per warp (warp tile 16x80)
#define BKS 64                 // K elems per stage (128B rows -> SW128)
#define KTN (HWX / BKS)        // 64 stages
#define NSTG 4
#define MATBA (BM_T * 128)     // 14KB A tile (112 rows x 128B)
#define MATBB (BN_T * 128)     // 20KB B tile (160 rows x 128B)
#define STGB (2 * MATBA + MATBB)   // 48KB
#define NT_TMA 448             // 14 warps: 7 along M x 2 along N
#define DYN_SMEM (NSTG * STGB + 1024)

__global__ void __launch_bounds__(NT_TMA, 1) gemm_tma(
    const __grid_constant__ CUtensorMap tmA1,
    const __grid_constant__ CUtensorMap tmA2,
    const __grid_constant__ CUtensorMap tmB,
    const float* __restrict__ pboxes, const float* __restrict__ tboxes,
    float* __restrict__ out) {
    extern __shared__ char dsm[];
    __shared__ TInfo sT[BN_T];
    __shared__ __align__(8) unsigned long long smbar[NSTG];

    uint32_t dbase = (smem_u32(dsm) + 1023) & ~1023u;
    uint32_t mb = smem_u32(smbar);

    int tid = threadIdx.x, lane = tid & 31, warp = tid >> 5;
    int n0 = blockIdx.x * BN_T, m0 = blockIdx.y * BM_T;
    int nvalid = min(BN_T, TT - n0);
    int wm = warp % 7, wn = warp / 7;
    int wr = wm * 16;            // 7 warps along M (16 rows each)
    int wc = wn * (NI * 8);      // 2 warps along N (80 cols each)

    if (tid == 0)
        for (int s = 0; s < NSTG; ++s) MBARRIER_INIT(mb + 8 * s, 1);
    fill_tinfo(sT, n0, tboxes, tid, BN_T);
    __syncthreads();

    if (tid == 0) {
#pragma unroll
        for (int s = 0; s < 3; ++s) {
            uint32_t fb = mb + 8 * s;
            MBARRIER_EXPECT_TX(fb, STGB);
            uint32_t d = dbase + s * STGB;
            int x = s * BKS;
            tma2d(d,             &tmA1, x, m0, fb);
            tma2d(d + MATBA,     &tmA2, x, m0, fb);
            tma2d(d + 2 * MATBA, &tmB,  x, n0, fb);
        }
    }

    float acc[2][NI][4];   // [mat][ni][frag], warp tile 16x80
#pragma unroll
    for (int a = 0; a < 2; ++a)
#pragma unroll
        for (int c = 0; c < NI; ++c)
#pragma unroll
            for (int d = 0; d < 4; ++d) acc[a][c][d] = 0.f;

    int a_row_l = (lane & 15);
    int a_coff  = (lane >> 4) * 16;          // bytes
    int b_row_l = (lane & 7) + ((lane >> 4) * 8);
    int b_coff  = ((lane >> 3) & 1) * 16;    // bytes

    uint32_t phases = 0;

    for (int kt = 0; kt < KTN; ++kt) {
        __syncthreads();   // all warps done reading slot (kt-1)&3
        if (tid == 0 && kt + 3 < KTN) {
            int sl = (kt + 3) & 3;
            uint32_t fb = mb + 8 * sl;
            MBARRIER_EXPECT_TX(fb, STGB);
            uint32_t d = dbase + sl * STGB;
            int x = (kt + 3) * BKS;
            tma2d(d,             &tmA1, x, m0, fb);
            tma2d(d + MATBA,     &tmA2, x, m0, fb);
            tma2d(d + 2 * MATBA, &tmB,  x, n0, fb);
        }
        int sl = kt & 3;
        MBARRIER_WAIT_PARITY(mb + 8 * sl, (phases >> sl) & 1);
        phases ^= 1u << sl;

        uint32_t sb = dbase + sl * STGB;
#pragma unroll
        for (int ks = 0; ks < 4; ++ks) {
            int cbyte = ks * 32;
            uint32_t af[2][4];
            {
                uint32_t off = (uint32_t)((wr + a_row_l) * 128 + cbyte + a_coff);
                uint32_t sw = SW128(off);
                ldsm_x4(af[0], sb + sw);
                ldsm_x4(af[1], sb + MATBA + sw);
            }
            uint32_t bf[NI][2];
#pragma unroll
            for (int nh = 0; nh < NI / 2; ++nh) {
                uint32_t regs[4];
                uint32_t off = (uint32_t)((wc + nh * 16 + b_row_l) * 128 + cbyte + b_coff);
                ldsm_x4(regs, sb + 2 * MATBA + SW128(off));
                bf[nh * 2][0] = regs[0]; bf[nh * 2][1] = regs[1];
                bf[nh * 2 + 1][0] = regs[2]; bf[nh * 2 + 1][1] = regs[3];
            }
#pragma unroll
            for (int s2 = 0; s2 < 2; ++s2)
#pragma unroll
                for (int ni = 0; ni < NI; ++ni)
                    mma16816(acc[s2][ni], af[s2], bf[ni]);
        }
    }

    // ---- fused cost epilogue (warp tile 16x80) ----
#pragma unroll
    for (int rh = 0; rh < 2; ++rh) {
        int p = m0 + wr + (lane >> 2) + rh * 8;
        if (p >= PP) continue;
        float snp_p = g_snp[p], psum_p = g_psum[p];
        float4 pb = *(const float4*)(pboxes + 4 * p);
        float px0 = pb.x - 0.5f * pb.z, py0 = pb.y - 0.5f * pb.w;
        float px1 = pb.x + 0.5f * pb.z, py1 = pb.y + 0.5f * pb.w;
        float parea = pb.z * pb.w;
        const float* prow = g_prob + (size_t)p * NC;
#pragma unroll
        for (int ni = 0; ni < NI; ++ni) {
            int tl0 = wc + ni * 8 + 2 * (lane & 3);
            if (tl0 >= nvalid) continue;
            float r2[2];
#pragma unroll
            for (int cc = 0; cc < 2; ++cc)
                r2[cc] = cost_elem(acc[0][ni][rh * 2 + cc], acc[1][ni][rh * 2 + cc],
                                   sT[tl0 + cc], pb, px0, py0, px1, py1, parea,
                                   snp_p, psum_p, prow);
            *(float2*)(out + (size_t)p * TT + n0 + tl0) = make_float2(r2[0], r2[1]);
        }
    }
}

// ---------------- GEMM path B: cp.async fallback (proven) ---------------------
#define BM 128
#define BN_F 128
#define BK 32
#define SAK 40
#define STAGES 4
#define KT_N (HWX / BK)
#define NT_FB 512
#define STAGE_ELEMS (3 * BM * SAK)
#define SMEM_BYTES_FB (STAGES * STAGE_ELEMS * 2 + BN_F * (int)sizeof(TInfo))

__global__ void __launch_bounds__(NT_FB, 1) gemm_cpasync(
    const float* __restrict__ pboxes, const float* __restrict__ tboxes,
    float* __restrict__ out) {
    extern __shared__ __align__(16) char smem_raw[];
    __nv_bfloat16* sBuf = (__nv_bfloat16*)smem_raw;
    TInfo* sT = (TInfo*)(smem_raw + STAGES * STAGE_ELEMS * 2);

    int tid = threadIdx.x, lane = tid & 31, warp = tid >> 5;
    int n0 = blockIdx.x * BN_F, m0 = blockIdx.y * BM;
    int nvalid = min(BN_F, TT - n0);
    int wr = (warp & 3) * 32;
    int wc = (warp >> 2) * 32;

    fill_tinfo(sT, n0, tboxes, tid, BN_F);

    float acc[2][2][4][4];
#pragma unroll
    for (int a = 0; a < 2; ++a)
#pragma unroll
        for (int b = 0; b < 2; ++b)
#pragma unroll
            for (int c = 0; c < 4; ++c)
#pragma unroll
                for (int d = 0; d < 4; ++d) acc[a][b][c][d] = 0.f;

    int a_row_l = (lane & 15);
    int a_col_l = (lane >> 4) * 8;
    int b_row_l = (lane & 7) + ((lane >> 4) * 8);
    int b_col_l = ((lane >> 3) & 1) * 8;

    auto loadStage = [&](int slot, int kt) {
        __nv_bfloat16* base = sBuf + slot * STAGE_ELEMS;
        int k0 = kt * BK;
#pragma unroll
        for (int it = 0; it < 3; ++it) {
            int i = tid + it * NT_FB;
            int mat = i >> 9;
            int rem = i & 511;
            int row = rem >> 2;
            int ch  = rem & 3;
            __nv_bfloat16* dst = base + mat * BM * SAK + row * SAK + ch * 8;
            const __nv_bfloat16* src;
            bool v;
            if (mat < 2) {
                int p = m0 + row;
                v = p < PP;
                const __nv_bfloat16* g = (mat == 0) ? g_A1 : g_A2;
                src = g + ((size_t)(v ? p : 0) * HWX + k0 + ch * 8);
            } else {
                int t = n0 + row;
                v = t < TT;
                src = g_tm + ((size_t)(v ? t : 0) * HWX + k0 + ch * 8);
            }
            cpa16(dst, src, v);
        }
        cpcommit();
    };

    loadStage(0, 0);
    loadStage(1, 1);
    loadStage(2, 2);

    for (int kt = 0; kt < KT_N; ++kt) {
        asm volatile("cp.async.wait_group 2;" ::: "memory");
        __syncthreads();
        int kl = kt + STAGES - 1;
        if (kl < KT_N) loadStage(kl & 3, kl);

        const __nv_bfloat16* S = sBuf + (kt & 3) * STAGE_ELEMS;
        uint32_t sbA1 = (uint32_t)__cvta_generic_to_shared(S);
        uint32_t sbA2 = sbA1 + BM * SAK * 2;
        uint32_t sbB  = sbA1 + 2 * BM * SAK * 2;
#pragma unroll
        for (int ks = 0; ks < 2; ++ks) {
            int cb = ks * 16;
            uint32_t af[2][2][4];
#pragma unroll
            for (int mi = 0; mi < 2; ++mi) {
                uint32_t ra = ((wr + mi * 16 + a_row_l) * SAK + cb + a_col_l) * 2;
                ldsm_x4(af[0][mi], sbA1 + ra);
                ldsm_x4(af[1][mi], sbA2 + ra);
            }
            uint32_t bf[4][2];
#pragma unroll
            for (int nh = 0; nh < 2; ++nh) {
                uint32_t regs[4];
                uint32_t rb = ((wc + nh * 16 + b_row_l) * SAK + cb + b_col_l) * 2;
                ldsm_x4(regs, sbB + rb);
                bf[nh * 2][0] = regs[0]; bf[nh * 2][1] = regs[1];
                bf[nh * 2 + 1][0] = regs[2]; bf[nh * 2 + 1][1] = regs[3];
            }
#pragma unroll
            for (int s2 = 0; s2 < 2; ++s2)
#pragma unroll
                for (int mi = 0; mi < 2; ++mi)
#pragma unroll
                    for (int ni = 0; ni < 4; ++ni)
                        mma16816(acc[s2][mi][ni], af[s2][mi], bf[ni]);
        }
    }

#pragma unroll
    for (int mi = 0; mi < 2; ++mi) {
#pragma unroll
        for (int rh = 0; rh < 2; ++rh) {
            int p = m0 + wr + mi * 16 + (lane >> 2) + rh * 8;
            if (p >= PP) continue;
            float snp_p = g_snp[p], psum_p = g_psum[p];
            float4 pb = *(const float4*)(pboxes + 4 * p);
            float px0 = pb.x - 0.5f * pb.z, py0 = pb.y - 0.5f * pb.w;
            float px1 = pb.x + 0.5f * pb.z, py1 = pb.y + 0.5f * pb.w;
            float parea = pb.z * pb.w;
            const float* prow = g_prob + (size_t)p * NC;
#pragma unroll
            for (int ni = 0; ni < 4; ++ni) {
                int tl0 = wc + ni * 8 + 2 * (lane & 3);
                if (tl0 >= nvalid) continue;
                float r2[2];
#pragma unroll
                for (int cc = 0; cc < 2; ++cc)
                    r2[cc] = cost_elem(acc[0][mi][ni][rh * 2 + cc], acc[1][mi][ni][rh * 2 + cc],
                                       sT[tl0 + cc], pb, px0, py0, px1, py1, parea,
                                       snp_p, psum_p, prow);
                *(float2*)(out + (size_t)p * TT + n0 + tl0) = make_float2(r2[0], r2[1]);
            }
        }
    }
}

// ---------------- host: tensormap encoding + launch ---------------------------
typedef CUresult (*PFN_encodeTiled)(
    CUtensorMap*, CUtensorMapDataType, cuuint32_t, void*,
    const cuuint64_t*, const cuuint64_t*, const cuuint32_t*, const cuuint32_t*,
    CUtensorMapInterleave, CUtensorMapSwizzle, CUtensorMapL2promotion,
    CUtensorMapFloatOOBfill);

static CUresult encode_map(PFN_encodeTiled enc, CUtensorMap* tm, void* ptr,
                           unsigned long long rows, unsigned box_rows) {
    cuuint64_t dims[2]    = {(cuuint64_t)HWX, (cuuint64_t)rows};
    cuuint64_t strides[1] = {(cuuint64_t)HWX * 2};
    cuuint32_t box[2]     = {BKS, box_rows};
    cuuint32_t estr[2]    = {1, 1};
    return enc(tm, CU_TENSOR_MAP_DATA_TYPE_BFLOAT16, 2, ptr, dims, strides, box, estr,
               CU_TENSOR_MAP_INTERLEAVE_NONE, CU_TENSOR_MAP_SWIZZLE_128B,
               CU_TENSOR_MAP_L2_PROMOTION_L2_128B, CU_TENSOR_MAP_FLOAT_OOB_FILL_NONE);
}

extern "C" void kernel_launch(void* const* d_in, const int* in_sizes, int n_in,
                              void* d_out, int out_size) {
    const float* pred_logits = (const float*)d_in[0];
    const float* pred_boxes  = (const float*)d_in[1];
    const float* pred_masks  = (const float*)d_in[2];
    const float* tgt_boxes   = (const float*)d_in[3];
    const float* tgt_masks   = (const float*)d_in[4];
    const void*  tgt_labels  = (const void*)d_in[5];
    float* out = (float*)d_out;

    aux_kernel<<<PP + TT + PP + 1, 256>>>(pred_logits, pred_masks, tgt_masks, tgt_labels);

    // Try the TMA path; verified fallback to the proven cp.async path.
    bool tma_ok = false;
    alignas(64) CUtensorMap tmA1, tmA2, tmB;
    void* fp = nullptr;
#if CUDART_VERSION >= 12000
    cudaDriverEntryPointQueryResult qr;
    cudaError_t e0 = cudaGetDriverEntryPoint("cuTensorMapEncodeTiled", &fp,
                                             cudaEnableDefault, &qr);
#else
    cudaError_t e0 = cudaGetDriverEntryPoint("cuTensorMapEncodeTiled", &fp,
                                             cudaEnableDefault);
#endif
    if (e0 == cudaSuccess && fp != nullptr) {
        PFN_encodeTiled enc = (PFN_encodeTiled)fp;
        void *pa1 = nullptr, *pa2 = nullptr, *pb = nullptr;
        cudaError_t s1 = cudaGetSymbolAddress(&pa1, g_A1);
        cudaError_t s2 = cudaGetSymbolAddress(&pa2, g_A2);
        cudaError_t s3 = cudaGetSymbolAddress(&pb,  g_tm);
        if (s1 == cudaSuccess && s2 == cudaSuccess && s3 == cudaSuccess) {
            CUresult r1 = encode_map(enc, &tmA1, pa1, PP, BM_T);
            CUresult r2 = encode_map(enc, &tmA2, pa2, PP, BM_T);
            CUresult r3 = encode_map(enc, &tmB,  pb,  TT, BN_T);
            tma_ok = (r1 == CUDA_SUCCESS && r2 == CUDA_SUCCESS && r3 == CUDA_SUCCESS);
        }
    }

    if (tma_ok) {
        dim3 grid((TT + BN_T - 1) / BN_T, (PP + BM_T - 1) / BM_T);   // 3 x 43 = 129
        cudaFuncSetAttribute(gemm_tma, cudaFuncAttributeMaxDynamicSharedMemorySize, DYN_SMEM);
        gemm_tma<<<grid, NT_TMA, DYN_SMEM>>>(tmA1, tmA2, tmB, pred_boxes, tgt_boxes, out);
    } else {
        dim3 grid((TT + BN_F - 1) / BN_F, (PP + BM - 1) / BM);       // 4 x 38 = 152
        cudaFuncSetAttribute(gemm_cpasync, cudaFuncAttributeMaxDynamicSharedMemorySize, SMEM_BYTES_FB);
        gemm_cpasync<<<grid, NT_FB, SMEM_BYTES_FB>>>(pred_boxes, tgt_boxes, out);
    }
}

// round 15
// speedup vs baseline: 2.0027x; 1.3805x over previous
#include <cuda_runtime.h>
#include <cuda.h>
#include <cuda_bf16.h>
#include <cstdint>
#include <math.h>

// Problem dims (fixed by the dataset)
#define BSZ 16
#define QQ  300
#define NC  81
#define HH  64
#define WWD 64
#define TT  400
#define HM  128
#define PP  (BSZ*QQ)     // 4800
#define HWX (HH*WWD)     // 4096

// ---------------- scratch (device globals; no allocation allowed) -------------
__device__ __align__(1024) int8_t g_A1q[(size_t)PP*HWX];   // quantized logits
__device__ __align__(1024) int8_t g_A2q[(size_t)PP*HWX];   // quantized sigmoid
__device__ __align__(1024) int8_t g_tmq[(size_t)TT*HWX];   // quantized resized targets
__device__ float g_tsum[TT];
__device__ float g_snp[PP];     // sum log_sigmoid(-m)
__device__ float g_psum[PP];    // sum sigmoid(m)
__device__ float g_scl[PP];     // maxm/(127*127) dequant factor for d1
__device__ float g_prob[(size_t)PP*NC];
__device__ int   g_lab[TT];     // decoded labels

// ---------------- small helpers -----------------------------------------------
__device__ __forceinline__ float block_reduce_sum(float v, float* sh) {
    int lane = threadIdx.x & 31, w = threadIdx.x >> 5;
#pragma unroll
    for (int o = 16; o; o >>= 1) v += __shfl_down_sync(0xffffffffu, v, o);
    if (lane == 0) sh[w] = v;
    __syncthreads();
    if (w == 0) {
        v = (lane < 8) ? sh[lane] : 0.f;
#pragma unroll
        for (int o = 4; o; o >>= 1) v += __shfl_down_sync(0xffffffffu, v, o);
    }
    return v;  // valid on thread 0
}

__device__ __forceinline__ float block_reduce_max(float v, float* sh) {
    int lane = threadIdx.x & 31, w = threadIdx.x >> 5;
#pragma unroll
    for (int o = 16; o; o >>= 1) v = fmaxf(v, __shfl_down_sync(0xffffffffu, v, o));
    if (lane == 0) sh[w] = v;
    __syncthreads();
    if (w == 0) {
        v = (lane < 8) ? sh[lane] : 0.f;
#pragma unroll
        for (int o = 4; o; o >>= 1) v = fmaxf(v, __shfl_down_sync(0xffffffffu, v, o));
    }
    return v;  // valid on thread 0
}

__device__ __forceinline__ void taps64(int i, int& j0, float w[4]) {
    if (i == 0)       { j0 = 0;   w[0] = 3.f/7.f; w[1] = 3.f/7.f; w[2] = 1.f/7.f; w[3] = 0.f; }
    else if (i == 63) { j0 = 124; w[0] = 0.f;     w[1] = 1.f/7.f; w[2] = 3.f/7.f; w[3] = 3.f/7.f; }
    else              { j0 = 2*i - 1; w[0] = 0.125f; w[1] = 0.375f; w[2] = 0.375f; w[3] = 0.125f; }
}

__device__ __forceinline__ uint32_t smem_u32(const void* p) {
    uint32_t a;
    asm("{ .reg .u64 t; cvta.to.shared.u64 t, %1; cvt.u32.u64 %0, t; }" : "=r"(a) : "l"(p));
    return a;
}

#define SW128(off) ((off) ^ (((off) >> 3) & 0x70))

__device__ __forceinline__ void cpa16(void* dst, const void* src, bool v) {
    uint32_t d = (uint32_t)__cvta_generic_to_shared(dst);
    int n = v ? 16 : 0;
    asm volatile("cp.async.cg.shared.global [%0], [%1], 16, %2;\n" :: "r"(d), "l"(src), "r"(n));
}
__device__ __forceinline__ void cpcommit() { asm volatile("cp.async.commit_group;\n"); }

// int8 MMA: m16n8k32 s8*s8 -> s32 (exact accumulation)
__device__ __forceinline__ void mma_s8(int c[4], const uint32_t a[4], const uint32_t b[2]) {
    asm volatile(
        "mma.sync.aligned.m16n8k32.row.col.s32.s8.s8.s32 "
        "{%0,%1,%2,%3}, {%4,%5,%6,%7}, {%8,%9}, {%0,%1,%2,%3};\n"
        : "+r"(c[0]), "+r"(c[1]), "+r"(c[2]), "+r"(c[3])
        : "r"(a[0]), "r"(a[1]), "r"(a[2]), "r"(a[3]), "r"(b[0]), "r"(b[1]));
}

__device__ __forceinline__ void ldsm_x4(uint32_t r[4], uint32_t addr) {
    asm volatile("ldmatrix.sync.aligned.m8n8.x4.shared.b16 {%0,%1,%2,%3}, [%4];"
        : "=r"(r[0]), "=r"(r[1]), "=r"(r[2]), "=r"(r[3]) : "r"(addr));
}

#define MBARRIER_INIT(addr, cnt) \
    asm volatile("mbarrier.init.shared.b64 [%0], %1;" :: "r"((uint32_t)(addr)), "r"((uint32_t)(cnt)) : "memory")

#define MBARRIER_EXPECT_TX(addr, tx) \
    asm volatile("mbarrier.arrive.expect_tx.shared.b64 _, [%0], %1;" :: "r"((uint32_t)(addr)), "r"((uint32_t)(tx)) : "memory")

#define MBARRIER_WAIT_PARITY(mbar_smem_addr, phase_parity) do { \
    uint32_t _mbar = (uint32_t)(mbar_smem_addr); \
    uint32_t _parity = (uint32_t)(phase_parity); \
    uint32_t _done; \
    asm volatile( \
        "{\n\t.reg .pred p;\n\t" \
        "mbarrier.try_wait.parity.acquire.cta.shared::cta.b64 p, [%1], %2;\n\t" \
        "selp.b32 %0, 1, 0, p;\n\t}" \
        : "=r"(_done) : "r"(_mbar), "r"(_parity) : "memory"); \
    if (!_done) { \
        asm volatile( \
            "{\n\t.reg .pred P1;\n\t" \
            "WAIT_LOOP_%=:\n\t" \
            "mbarrier.try_wait.parity.acquire.cta.shared::cta.b64 P1, [%0], %1, 0x989680;\n\t" \
            "@P1 bra.uni WAIT_DONE_%=;\n\t" \
            "bra.uni WAIT_LOOP_%=;\n\t" \
            "WAIT_DONE_%=:\n\t}" \
            :: "r"(_mbar), "r"(_parity) : "memory"); \
    } \
} while (0)

__device__ __forceinline__ void tma2d(uint32_t dst, const CUtensorMap* tmap,
                                      int x, int y, uint32_t mbar) {
    asm volatile(
        "cp.async.bulk.tensor.2d.shared::cta.global.tile.mbarrier::complete_tx::bytes "
        "[%0], [%1, {%2, %3}], [%4];"
        :: "r"(dst), "l"(tmap), "r"(x), "r"(y), "r"(mbar) : "memory");
}

__device__ __forceinline__ int q8(float x) {
    int q = __float2int_rn(x);
    return max(-127, min(127, q));
}
__device__ __forceinline__ uint32_t pack4(int a, int b, int c, int d) {
    return (uint32_t)(a & 0xff) | ((uint32_t)(b & 0xff) << 8)
         | ((uint32_t)(c & 0xff) << 16) | ((uint32_t)(d & 0xff) << 24);
}

// ---------------- fused aux kernel (label + resize + prep + prob) -------------
__global__ void __launch_bounds__(256) aux_kernel(
    const float* __restrict__ logits, const float* __restrict__ masks,
    const float* __restrict__ tmasks, const void* __restrict__ labels) {
    __shared__ __align__(16) char smr[HM * HH * 4];   // 32KB, branch-dependent use
    __shared__ float red[8];
    __shared__ float sbcast;
    int bid = blockIdx.x, tid = threadIdx.x;

    if (bid < PP) {
        // ---- prep: quantize logits+sigmoid to int8 with per-row scale ----
        int p = bid;
        const float4* src = (const float4*)(masks + (size_t)p * HWX);
        float* sm_m = (float*)smr;        // 4096 floats
        float* sm_s = sm_m + HWX;         // 4096 floats (total 32KB)
        float accn = 0.f, accs = 0.f, amax = 0.f;
        for (int i = tid; i < HWX / 4; i += 256) {
            float4 v = src[i];
            float m[4] = {v.x, v.y, v.z, v.w};
#pragma unroll
            for (int j = 0; j < 4; ++j) {
                float am = fabsf(m[j]);
                float e = __expf(-am);
                float r = __fdividef(1.f, 1.f + e);
                float s = (m[j] >= 0.f) ? r : e * r;
                accn -= (fmaxf(m[j], 0.f) + __logf(1.f + e));
                accs += s;
                amax = fmaxf(amax, am);
                sm_m[4 * i + j] = m[j];
                sm_s[4 * i + j] = s;
            }
        }
        float tn = block_reduce_sum(accn, red);
        __syncthreads();
        float ts = block_reduce_sum(accs, red);
        __syncthreads();
        float mx = block_reduce_max(amax, red);
        if (tid == 0) {
            sbcast = fmaxf(mx, 1e-20f);
            g_snp[p] = tn; g_psum[p] = ts;
            g_scl[p] = fmaxf(mx, 1e-20f) * (1.f / 16129.f);
        }
        __syncthreads();
        float scale = __fdividef(127.f, sbcast);
        uint32_t* d1 = (uint32_t*)(g_A1q + (size_t)p * HWX);
        uint32_t* d2 = (uint32_t*)(g_A2q + (size_t)p * HWX);
        for (int i = tid; i < HWX / 4; i += 256) {
            int qm[4], qs[4];
#pragma unroll
            for (int j = 0; j < 4; ++j) {
                qm[j] = q8(sm_m[4 * i + j] * scale);
                qs[j] = q8(sm_s[4 * i + j] * 127.f);
            }
            d1[i] = pack4(qm[0], qm[1], qm[2], qm[3]);
            d2[i] = pack4(qs[0], qs[1], qs[2], qs[3]);
        }
    } else if (bid < PP + TT) {
        // ---- resize target masks 128->64 + row sums + int8 quantize ----
        int t = bid - PP;
        const float* src = tmasks + (size_t)t * HM * HM;
        float (*htmp)[HH] = (float(*)[HH])smr;
        for (int e = tid; e < HM * HH; e += 256) {
            int r = e >> 6, i = e & 63;
            int j0; float w[4]; taps64(i, j0, w);
            const float* row = src + r * HM;
            htmp[r][i] = w[0]*row[j0] + w[1]*row[j0+1] + w[2]*row[j0+2] + w[3]*row[j0+3];
        }
        __syncthreads();
        float lsum = 0.f;
        for (int e = tid; e < HWX; e += 256) {
            int o = e >> 6, i = e & 63;
            int j0; float w[4]; taps64(o, j0, w);
            float v = w[0]*htmp[j0][i] + w[1]*htmp[j0+1][i] + w[2]*htmp[j0+2][i] + w[3]*htmp[j0+3][i];
            g_tmq[(size_t)t * HWX + e] = (int8_t)q8(v * 127.f);
            lsum += v;
        }
        __syncthreads();
        float tot = block_reduce_sum(lsum, red);
        if (tid == 0) g_tsum[t] = tot;
    } else if (bid < PP + TT + PP) {
        // ---- softmax probs over 81 classes ----
        int p = bid - PP - TT;
        float* sh = (float*)smr;
        float x = (tid < NC) ? logits[(size_t)p * NC + tid] : -1e30f;
        if (tid < 128) sh[tid] = x;
        __syncthreads();
        for (int s = 64; s > 0; s >>= 1) { if (tid < s) sh[tid] = fmaxf(sh[tid], sh[tid + s]); __syncthreads(); }
        float mx = sh[0]; __syncthreads();
        float e = (tid < NC) ? __expf(x - mx) : 0.f;
        if (tid < 128) sh[tid] = e;
        __syncthreads();
        for (int s = 64; s > 0; s >>= 1) { if (tid < s) sh[tid] += sh[tid + s]; __syncthreads(); }
        float inv = __fdividef(1.f, sh[0]);
        if (tid < NC) g_prob[(size_t)p * NC + tid] = e * inv;
    } else {
        // ---- label decode (robust to int32/int64) ----
        __shared__ int odd_nz;
        if (tid == 0) odd_nz = 0;
        __syncthreads();
        const int* li = (const int*)labels;
        for (int i = tid; i < TT / 2; i += 256)
            if (li[2 * i + 1] != 0) atomicOr(&odd_nz, 1);
        __syncthreads();
        bool is64 = (odd_nz == 0);
        for (int t = tid; t < TT; t += 256)
            g_lab[t] = is64 ? (int)((const long long*)labels)[t] : li[t];
    }
}

// ---------------- shared epilogue pieces --------------------------------------
struct TInfo {
    float cx, cy, w, h, x0, y0, x1, y1, area, tsum;
    int lab, pad;
};

__device__ __forceinline__ void fill_tinfo(TInfo* sT, int n0, const float* tboxes,
                                           int tid, int cnt) {
    for (int i = tid; i < cnt; i += blockDim.x) {
        int t = n0 + i;
        TInfo ti;
        if (t < TT) {
            float4 tb = *(const float4*)(tboxes + 4 * t);
            ti.cx = tb.x; ti.cy = tb.y; ti.w = tb.z; ti.h = tb.w;
            ti.x0 = tb.x - 0.5f * tb.z; ti.y0 = tb.y - 0.5f * tb.w;
            ti.x1 = tb.x + 0.5f * tb.z; ti.y1 = tb.y + 0.5f * tb.w;
            ti.area = tb.z * tb.w;
            ti.tsum = g_tsum[t];
            ti.lab = g_lab[t];
        } else {
            ti.cx = ti.cy = ti.w = ti.h = 0.f;
            ti.x0 = ti.y0 = ti.x1 = ti.y1 = 0.f;
            ti.area = ti.tsum = 0.f; ti.lab = 0;
        }
        ti.pad = 0;
        sT[i] = ti;
    }
}

__device__ __forceinline__ float cost_elem(
    float d1, float d2, const TInfo& ti, const float4& pb,
    float px0, float py0, float px1, float py1, float parea,
    float snp_p, float psum_p, const float* prow) {
    const float inv_hw = 1.0f / (float)HWX;
    float l1 = fabsf(pb.x - ti.cx) + fabsf(pb.y - ti.cy)
             + fabsf(pb.z - ti.w) + fabsf(pb.w - ti.h);
    float ix0 = fmaxf(px0, ti.x0), iy0 = fmaxf(py0, ti.y0);
    float ix1 = fminf(px1, ti.x1), iy1 = fminf(py1, ti.y1);
    float inter = fmaxf(ix1 - ix0, 0.f) * fmaxf(iy1 - iy0, 0.f);
    float uni = parea + ti.area - inter;
    float iou = inter / uni;
    float ex0 = fminf(px0, ti.x0), ey0 = fminf(py0, ti.y0);
    float ex1 = fmaxf(px1, ti.x1), ey1 = fmaxf(py1, ti.y1);
    float enc = fmaxf(ex1 - ex0, 0.f) * fmaxf(ey1 - ey0, 0.f);
    float giou = iou - (enc - uni) / enc;
    float cmask = -(d1 + snp_p) * inv_hw;
    float cdice = 1.f - (2.f * d2 + 1e-5f) / (psum_p + ti.tsum + 1e-5f);
    float ccls = -prow[ti.lab];
    return 5.f * l1 - 2.f * giou + 2.f * ccls + 5.f * cmask + 5.f * cdice;
}

// ---------------- GEMM: int8 TMA, 129 CTAs single wave, 14 warps ---------------
#define BM_T 112               // 43 m-tiles x 3 n-tiles = 129 CTAs <= 148 SMs
#define BN_T 160
#define NI 10                  // n8 frags per warp (warp tile 16x80)
#define BKS 128                // K elems per stage (128B rows of s8 -> SW128)
#define KTN (HWX / BKS)        // 32 stages
#define NSTG 4
#define MATBA (BM_T * 128)     // 14KB A tile (112 rows x 128B)
#define MATBB (BN_T * 128)     // 20KB B tile (160 rows x 128B)
#define STGB (2 * MATBA + MATBB)   // 48KB
#define NT_TMA 448             // 14 warps: 7 along M x 2 along N
#define DYN_SMEM (NSTG * STGB + 1024)

__global__ void __launch_bounds__(NT_TMA, 1) gemm_tma(
    const __grid_constant__ CUtensorMap tmA1,
    const __grid_constant__ CUtensorMap tmA2,
    const __grid_constant__ CUtensorMap tmB,
    const float* __restrict__ pboxes, const float* __restrict__ tboxes,
    float* __restrict__ out) {
    extern __shared__ char dsm[];
    __shared__ TInfo sT[BN_T];
    __shared__ __align__(8) unsigned long long smbar[NSTG];

    uint32_t dbase = (smem_u32(dsm) + 1023) & ~1023u;
    uint32_t mb = smem_u32(smbar);

    int tid = threadIdx.x, lane = tid & 31, warp = tid >> 5;
    int n0 = blockIdx.x * BN_T, m0 = blockIdx.y * BM_T;
    int nvalid = min(BN_T, TT - n0);
    int wm = warp % 7, wn = warp / 7;
    int wr = wm * 16;            // 7 warps along M (16 rows each)
    int wc = wn * (NI * 8);      // 2 warps along N (80 cols each)

    if (tid == 0)
        for (int s = 0; s < NSTG; ++s) MBARRIER_INIT(mb + 8 * s, 1);
    fill_tinfo(sT, n0, tboxes, tid, BN_T);
    __syncthreads();

    if (tid == 0) {
#pragma unroll
        for (int s = 0; s < 3; ++s) {
            uint32_t fb = mb + 8 * s;
            MBARRIER_EXPECT_TX(fb, STGB);
            uint32_t d = dbase + s * STGB;
            int x = s * BKS;
            tma2d(d,             &tmA1, x, m0, fb);
            tma2d(d + MATBA,     &tmA2, x, m0, fb);
            tma2d(d + 2 * MATBA, &tmB,  x, n0, fb);
        }
    }

    int acc[2][NI][4];   // [mat][ni][frag] s32, warp tile 16x80
#pragma unroll
    for (int a = 0; a < 2; ++a)
#pragma unroll
        for (int c = 0; c < NI; ++c)
#pragma unroll
            for (int d = 0; d < 4; ++d) acc[a][c][d] = 0;

    int a_row_l = (lane & 15);
    int a_coff  = (lane >> 4) * 16;          // bytes
    int b_row_l = (lane & 7) + ((lane >> 4) * 8);
    int b_coff  = ((lane >> 3) & 1) * 16;    // bytes

    uint32_t phases = 0;

    for (int kt = 0; kt < KTN; ++kt) {
        __syncthreads();   // all warps done reading slot (kt-1)&3
        if (tid == 0 && kt + 3 < KTN) {
            int sl = (kt + 3) & 3;
            uint32_t fb = mb + 8 * sl;
            MBARRIER_EXPECT_TX(fb, STGB);
            uint32_t d = dbase + sl * STGB;
            int x = (kt + 3) * BKS;
            tma2d(d,             &tmA1, x, m0, fb);
            tma2d(d + MATBA,     &tmA2, x, m0, fb);
            tma2d(d + 2 * MATBA, &tmB,  x, n0, fb);
        }
        int sl = kt & 3;
        MBARRIER_WAIT_PARITY(mb + 8 * sl, (phases >> sl) & 1);
        phases ^= 1u << sl;

        uint32_t sb = dbase + sl * STGB;
#pragma unroll
        for (int ks = 0; ks < 4; ++ks) {   // 4 x k32 per 128B stage row
            int cbyte = ks * 32;
            uint32_t af[2][4];
            {
                uint32_t off = (uint32_t)((wr + a_row_l) * 128 + cbyte + a_coff);
                uint32_t sw = SW128(off);
                ldsm_x4(af[0], sb + sw);
                ldsm_x4(af[1], sb + MATBA + sw);
            }
            uint32_t bf[NI][2];
#pragma unroll
            for (int nh = 0; nh < NI / 2; ++nh) {
                uint32_t regs[4];
                uint32_t off = (uint32_t)((wc + nh * 16 + b_row_l) * 128 + cbyte + b_coff);
                ldsm_x4(regs, sb + 2 * MATBA + SW128(off));
                bf[nh * 2][0] = regs[0]; bf[nh * 2][1] = regs[1];
                bf[nh * 2 + 1][0] = regs[2]; bf[nh * 2 + 1][1] = regs[3];
            }
#pragma unroll
            for (int s2 = 0; s2 < 2; ++s2)
#pragma unroll
                for (int ni = 0; ni < NI; ++ni)
                    mma_s8(acc[s2][ni], af[s2], bf[ni]);
        }
    }

    // ---- fused cost epilogue (warp tile 16x80, s32 -> float dequant) ----
    const float inv127sq = 1.f / 16129.f;
#pragma unroll
    for (int rh = 0; rh < 2; ++rh) {
        int p = m0 + wr + (lane >> 2) + rh * 8;
        if (p >= PP) continue;
        float snp_p = g_snp[p], psum_p = g_psum[p];
        float f1p = g_scl[p];
        float4 pb = *(const float4*)(pboxes + 4 * p);
        float px0 = pb.x - 0.5f * pb.z, py0 = pb.y - 0.5f * pb.w;
        float px1 = pb.x + 0.5f * pb.z, py1 = pb.y + 0.5f * pb.w;
        float parea = pb.z * pb.w;
        const float* prow = g_prob + (size_t)p * NC;
#pragma unroll
        for (int ni = 0; ni < NI; ++ni) {
            int tl0 = wc + ni * 8 + 2 * (lane & 3);
            if (tl0 >= nvalid) continue;
            float r2[2];
#pragma unroll
            for (int cc = 0; cc < 2; ++cc) {
                float d1 = (float)acc[0][ni][rh * 2 + cc] * f1p;
                float d2 = (float)acc[1][ni][rh * 2 + cc] * inv127sq;
                r2[cc] = cost_elem(d1, d2, sT[tl0 + cc], pb, px0, py0, px1, py1, parea,
                                   snp_p, psum_p, prow);
            }
            *(float2*)(out + (size_t)p * TT + n0 + tl0) = make_float2(r2[0], r2[1]);
        }
    }
}

// ---------------- GEMM path B: cp.async fallback (same layout/compute) ---------
__global__ void __launch_bounds__(NT_TMA, 1) gemm_cpasync(
    const float* __restrict__ pboxes, const float* __restrict__ tboxes,
    float* __restrict__ out) {
    extern __shared__ char dsm[];
    __shared__ TInfo sT[BN_T];

    uint32_t dbase = (smem_u32(dsm) + 1023) & ~1023u;
    char* dgen = (char*)dsm + (dbase - smem_u32(dsm));   // generic ptr matching dbase

    int tid = threadIdx.x, lane = tid & 31, warp = tid >> 5;
    int n0 = blockIdx.x * BN_T, m0 = blockIdx.y * BM_T;
    int nvalid = min(BN_T, TT - n0);
    int wm = warp % 7, wn = warp / 7;
    int wr = wm * 16;
    int wc = wn * (NI * 8);

    fill_tinfo(sT, n0, tboxes, tid, BN_T);

    int acc[2][NI][4];
#pragma unroll
    for (int a = 0; a < 2; ++a)
#pragma unroll
        for (int c = 0; c < NI; ++c)
#pragma unroll
            for (int d = 0; d < 4; ++d) acc[a][c][d] = 0;

    int a_row_l = (lane & 15);
    int a_coff  = (lane >> 4) * 16;
    int b_row_l = (lane & 7) + ((lane >> 4) * 8);
    int b_coff  = ((lane >> 3) & 1) * 16;

    // stage: (112+112+160) rows x 8 chunks(16B) = 3072 cp.async
    auto loadStage = [&](int slot, int kt) {
        char* base = dgen + slot * STGB;
        int k0 = kt * BKS;
        for (int i = tid; i < 3072; i += NT_TMA) {
            int ch = i & 7;
            int r = i >> 3;      // 0..383
            int mat, row;
            if (r < BM_T)            { mat = 0; row = r; }
            else if (r < 2 * BM_T)   { mat = 1; row = r - BM_T; }
            else                     { mat = 2; row = r - 2 * BM_T; }
            char* dst = base + ((mat == 0) ? 0 : (mat == 1) ? MATBA : 2 * MATBA)
                      + SW128(row * 128 + ch * 16);
            const int8_t* src;
            bool v;
            if (mat < 2) {
                int p = m0 + row;
                v = p < PP;
                const int8_t* g = (mat == 0) ? g_A1q : g_A2q;
                src = g + ((size_t)(v ? p : 0) * HWX + k0 + ch * 16);
            } else {
                int t = n0 + row;
                v = t < TT;
                src = g_tmq + ((size_t)(v ? t : 0) * HWX + k0 + ch * 16);
            }
            cpa16(dst, src, v);
        }
        cpcommit();
    };

    loadStage(0, 0);
    loadStage(1, 1);
    loadStage(2, 2);

    for (int kt = 0; kt < KTN; ++kt) {
        asm volatile("cp.async.wait_group 2;" ::: "memory");
        __syncthreads();
        int kl = kt + NSTG - 1;
        if (kl < KTN) loadStage(kl & 3, kl);

        uint32_t sb = dbase + (kt & 3) * STGB;
#pragma unroll
        for (int ks = 0; ks < 4; ++ks) {
            int cbyte = ks * 32;
            uint32_t af[2][4];
            {
                uint32_t off = (uint32_t)((wr + a_row_l) * 128 + cbyte + a_coff);
                uint32_t sw = SW128(off);
                ldsm_x4(af[0], sb + sw);
                ldsm_x4(af[1], sb + MATBA + sw);
            }
            uint32_t bf[NI][2];
#pragma unroll
            for (int nh = 0; nh < NI / 2; ++nh) {
                uint32_t regs[4];
                uint32_t off = (uint32_t)((wc + nh * 16 + b_row_l) * 128 + cbyte + b_coff);
                ldsm_x4(regs, sb + 2 * MATBA + SW128(off));
                bf[nh * 2][0] = regs[0]; bf[nh * 2][1] = regs[1];
                bf[nh * 2 + 1][0] = regs[2]; bf[nh * 2 + 1][1] = regs[3];
            }
#pragma unroll
            for (int s2 = 0; s2 < 2; ++s2)
#pragma unroll
                for (int ni = 0; ni < NI; ++ni)
                    mma_s8(acc[s2][ni], af[s2], bf[ni]);
        }
    }

    const float inv127sq = 1.f / 16129.f;
#pragma unroll
    for (int rh = 0; rh < 2; ++rh) {
        int p = m0 + wr + (lane >> 2) + rh * 8;
        if (p >= PP) continue;
        float snp_p = g_snp[p], psum_p = g_psum[p];
        float f1p = g_scl[p];
        float4 pb = *(const float4*)(pboxes + 4 * p);
        float px0 = pb.x - 0.5f * pb.z, py0 = pb.y - 0.5f * pb.w;
        float px1 = pb.x + 0.5f * pb.z, py1 = pb.y + 0.5f * pb.w;
        float parea = pb.z * pb.w;
        const float* prow = g_prob + (size_t)p * NC;
#pragma unroll
        for (int ni = 0; ni < NI; ++ni) {
            int tl0 = wc + ni * 8 + 2 * (lane & 3);
            if (tl0 >= nvalid) continue;
            float r2[2];
#pragma unroll
            for (int cc = 0; cc < 2; ++cc) {
                float d1 = (float)acc[0][ni][rh * 2 + cc] * f1p;
                float d2 = (float)acc[1][ni][rh * 2 + cc] * inv127sq;
                r2[cc] = cost_elem(d1, d2, sT[tl0 + cc], pb, px0, py0, px1, py1, parea,
                                   snp_p, psum_p, prow);
            }
            *(float2*)(out + (size_t)p * TT + n0 + tl0) = make_float2(r2[0], r2[1]);
        }
    }
}

// ---------------- host: tensormap encoding + launch ---------------------------
typedef CUresult (*PFN_encodeTiled)(
    CUtensorMap*, CUtensorMapDataType, cuuint32_t, void*,
    const cuuint64_t*, const cuuint64_t*, const cuuint32_t*, const cuuint32_t*,
    CUtensorMapInterleave, CUtensorMapSwizzle, CUtensorMapL2promotion,
    CUtensorMapFloatOOBfill);

static CUresult encode_map(PFN_encodeTiled enc, CUtensorMap* tm, void* ptr,
                           unsigned long long rows, unsigned box_rows) {
    cuuint64_t dims[2]    = {(cuuint64_t)HWX, (cuuint64_t)rows};
    cuuint64_t strides[1] = {(cuuint64_t)HWX};          // bytes (int8)
    cuuint32_t box[2]     = {BKS, box_rows};            // 128 x rows
    cuuint32_t estr[2]    = {1, 1};
    return enc(tm, CU_TENSOR_MAP_DATA_TYPE_UINT8, 2, ptr, dims, strides, box, estr,
               CU_TENSOR_MAP_INTERLEAVE_NONE, CU_TENSOR_MAP_SWIZZLE_128B,
               CU_TENSOR_MAP_L2_PROMOTION_L2_128B, CU_TENSOR_MAP_FLOAT_OOB_FILL_NONE);
}

extern "C" void kernel_launch(void* const* d_in, const int* in_sizes, int n_in,
                              void* d_out, int out_size) {
    const float* pred_logits = (const float*)d_in[0];
    const float* pred_boxes  = (const float*)d_in[1];
    const float* pred_masks  = (const float*)d_in[2];
    const float* tgt_boxes   = (const float*)d_in[3];
    const float* tgt_masks   = (const float*)d_in[4];
    const void*  tgt_labels  = (const void*)d_in[5];
    float* out = (float*)d_out;

    aux_kernel<<<PP + TT + PP + 1, 256>>>(pred_logits, pred_masks, tgt_masks, tgt_labels);

    // Try the TMA path; verified fallback to cp.async path.
    bool tma_ok = false;
    alignas(64) CUtensorMap tmA1, tmA2, tmB;
    void* fp = nullptr;
#if CUDART_VERSION >= 12000
    cudaDriverEntryPointQueryResult qr;
    cudaError_t e0 = cudaGetDriverEntryPoint("cuTensorMapEncodeTiled", &fp,
                                             cudaEnableDefault, &qr);
#else
    cudaError_t e0 = cudaGetDriverEntryPoint("cuTensorMapEncodeTiled", &fp,
                                             cudaEnableDefault);
#endif
    if (e0 == cudaSuccess && fp != nullptr) {
        PFN_encodeTiled enc = (PFN_encodeTiled)fp;
        void *pa1 = nullptr, *pa2 = nullptr, *pb = nullptr;
        cudaError_t s1 = cudaGetSymbolAddress(&pa1, g_A1q);
        cudaError_t s2 = cudaGetSymbolAddress(&pa2, g_A2q);
        cudaError_t s3 = cudaGetSymbolAddress(&pb,  g_tmq);
        if (s1 == cudaSuccess && s2 == cudaSuccess && s3 == cudaSuccess) {
            CUresult r1 = encode_map(enc, &tmA1, pa1, PP, BM_T);
            CUresult r2 = encode_map(enc, &tmA2, pa2, PP, BM_T);
            CUresult r3 = encode_map(enc, &tmB,  pb,  TT, BN_T);
            tma_ok = (r1 == CUDA_SUCCESS && r2 == CUDA_SUCCESS && r3 == CUDA_SUCCESS);
        }
    }

    dim3 grid((TT + BN_T - 1) / BN_T, (PP + BM_T - 1) / BM_T);   // 3 x 43 = 129
    if (tma_ok) {
        cudaFuncSetAttribute(gemm_tma, cudaFuncAttributeMaxDynamicSharedMemorySize, DYN_SMEM);
        gemm_tma<<<grid, NT_TMA, DYN_SMEM>>>(tmA1, tmA2, tmB, pred_boxes, tgt_boxes, out);
    } else {
        cudaFuncSetAttribute(gemm_cpasync, cudaFuncAttributeMaxDynamicSharedMemorySize, DYN_SMEM);
        gemm_cpasync<<<grid, NT_TMA, DYN_SMEM>>>(pred_boxes, tgt_boxes, out);
    }
}

// round 16
// speedup vs baseline: 2.0689x; 1.0330x over previous
#include <cuda_runtime.h>
#include <cuda.h>
#include <cuda_bf16.h>
#include <cstdint>
#include <math.h>

// Problem dims (fixed by the dataset)
#define BSZ 16
#define QQ  300
#define NC  81
#define HH  64
#define WWD 64
#define TT  400
#define HM  128
#define PP  (BSZ*QQ)     // 4800
#define HWX (HH*WWD)     // 4096

// ---------------- scratch (device globals; no allocation allowed) -------------
__device__ __align__(1024) int8_t g_A1q[(size_t)PP*HWX];   // quantized logits
__device__ __align__(1024) int8_t g_A2q[(size_t)PP*HWX];   // quantized sigmoid
__device__ __align__(1024) int8_t g_tmq[(size_t)TT*HWX];   // quantized resized targets
__device__ float g_tsum[TT];
__device__ float g_snp[PP];     // sum log_sigmoid(-m)
__device__ float g_psum[PP];    // sum sigmoid(m)
__device__ float g_scl[PP];     // maxm/(127*127) dequant factor for d1
__device__ float g_prob[(size_t)PP*NC];
__device__ int   g_lab[TT];     // decoded labels

// ---------------- small helpers -----------------------------------------------
__device__ __forceinline__ float block_reduce_sum(float v, float* sh) {
    int lane = threadIdx.x & 31, w = threadIdx.x >> 5;
#pragma unroll
    for (int o = 16; o; o >>= 1) v += __shfl_down_sync(0xffffffffu, v, o);
    if (lane == 0) sh[w] = v;
    __syncthreads();
    if (w == 0) {
        v = (lane < 8) ? sh[lane] : 0.f;
#pragma unroll
        for (int o = 4; o; o >>= 1) v += __shfl_down_sync(0xffffffffu, v, o);
    }
    return v;  // valid on thread 0
}

__device__ __forceinline__ float block_reduce_max(float v, float* sh) {
    int lane = threadIdx.x & 31, w = threadIdx.x >> 5;
#pragma unroll
    for (int o = 16; o; o >>= 1) v = fmaxf(v, __shfl_down_sync(0xffffffffu, v, o));
    if (lane == 0) sh[w] = v;
    __syncthreads();
    if (w == 0) {
        v = (lane < 8) ? sh[lane] : 0.f;
#pragma unroll
        for (int o = 4; o; o >>= 1) v = fmaxf(v, __shfl_down_sync(0xffffffffu, v, o));
    }
    return v;  // valid on thread 0
}

__device__ __forceinline__ void taps64(int i, int& j0, float w[4]) {
    if (i == 0)       { j0 = 0;   w[0] = 3.f/7.f; w[1] = 3.f/7.f; w[2] = 1.f/7.f; w[3] = 0.f; }
    else if (i == 63) { j0 = 124; w[0] = 0.f;     w[1] = 1.f/7.f; w[2] = 3.f/7.f; w[3] = 3.f/7.f; }
    else              { j0 = 2*i - 1; w[0] = 0.125f; w[1] = 0.375f; w[2] = 0.375f; w[3] = 0.125f; }
}

__device__ __forceinline__ uint32_t smem_u32(const void* p) {
    uint32_t a;
    asm("{ .reg .u64 t; cvta.to.shared.u64 t, %1; cvt.u32.u64 %0, t; }" : "=r"(a) : "l"(p));
    return a;
}

#define SW128(off) ((off) ^ (((off) >> 3) & 0x70))

__device__ __forceinline__ void cpa16(void* dst, const void* src, bool v) {
    uint32_t d = (uint32_t)__cvta_generic_to_shared(dst);
    int n = v ? 16 : 0;
    asm volatile("cp.async.cg.shared.global [%0], [%1], 16, %2;\n" :: "r"(d), "l"(src), "r"(n));
}
__device__ __forceinline__ void cpcommit() { asm volatile("cp.async.commit_group;\n"); }

// int8 MMA: m16n8k32 s8*s8 -> s32 (exact accumulation)
__device__ __forceinline__ void mma_s8(int c[4], const uint32_t a[4], const uint32_t b[2]) {
    asm volatile(
        "mma.sync.aligned.m16n8k32.row.col.s32.s8.s8.s32 "
        "{%0,%1,%2,%3}, {%4,%5,%6,%7}, {%8,%9}, {%0,%1,%2,%3};\n"
        : "+r"(c[0]), "+r"(c[1]), "+r"(c[2]), "+r"(c[3])
        : "r"(a[0]), "r"(a[1]), "r"(a[2]), "r"(a[3]), "r"(b[0]), "r"(b[1]));
}

__device__ __forceinline__ void ldsm_x4(uint32_t r[4], uint32_t addr) {
    asm volatile("ldmatrix.sync.aligned.m8n8.x4.shared.b16 {%0,%1,%2,%3}, [%4];"
        : "=r"(r[0]), "=r"(r[1]), "=r"(r[2]), "=r"(r[3]) : "r"(addr));
}

#define MBARRIER_INIT(addr, cnt) \
    asm volatile("mbarrier.init.shared.b64 [%0], %1;" :: "r"((uint32_t)(addr)), "r"((uint32_t)(cnt)) : "memory")

#define MBARRIER_EXPECT_TX(addr, tx) \
    asm volatile("mbarrier.arrive.expect_tx.shared.b64 _, [%0], %1;" :: "r"((uint32_t)(addr)), "r"((uint32_t)(tx)) : "memory")

#define MBARRIER_WAIT_PARITY(mbar_smem_addr, phase_parity) do { \
    uint32_t _mbar = (uint32_t)(mbar_smem_addr); \
    uint32_t _parity = (uint32_t)(phase_parity); \
    uint32_t _done; \
    asm volatile( \
        "{\n\t.reg .pred p;\n\t" \
        "mbarrier.try_wait.parity.acquire.cta.shared::cta.b64 p, [%1], %2;\n\t" \
        "selp.b32 %0, 1, 0, p;\n\t}" \
        : "=r"(_done) : "r"(_mbar), "r"(_parity) : "memory"); \
    if (!_done) { \
        asm volatile( \
            "{\n\t.reg .pred P1;\n\t" \
            "WAIT_LOOP_%=:\n\t" \
            "mbarrier.try_wait.parity.acquire.cta.shared::cta.b64 P1, [%0], %1, 0x989680;\n\t" \
            "@P1 bra.uni WAIT_DONE_%=;\n\t" \
            "bra.uni WAIT_LOOP_%=;\n\t" \
            "WAIT_DONE_%=:\n\t}" \
            :: "r"(_mbar), "r"(_parity) : "memory"); \
    } \
} while (0)

__device__ __forceinline__ void tma2d(uint32_t dst, const CUtensorMap* tmap,
                                      int x, int y, uint32_t mbar) {
    asm volatile(
        "cp.async.bulk.tensor.2d.shared::cta.global.tile.mbarrier::complete_tx::bytes "
        "[%0], [%1, {%2, %3}], [%4];"
        :: "r"(dst), "l"(tmap), "r"(x), "r"(y), "r"(mbar) : "memory");
}

__device__ __forceinline__ int q8(float x) {
    int q = __float2int_rn(x);
    return max(-127, min(127, q));
}
__device__ __forceinline__ uint32_t pack4(int a, int b, int c, int d) {
    return (uint32_t)(a & 0xff) | ((uint32_t)(b & 0xff) << 8)
         | ((uint32_t)(c & 0xff) << 16) | ((uint32_t)(d & 0xff) << 24);
}

// ---------------- fused aux kernel (prep+softmax | resize | label) ------------
__global__ void __launch_bounds__(256) aux_kernel(
    const float* __restrict__ logits, const float* __restrict__ masks,
    const float* __restrict__ tmasks, const void* __restrict__ labels) {
    __shared__ __align__(16) char smr[HM * HH * 4];   // 32KB (resize branch only)
    __shared__ float red[8];
    __shared__ float sbcast;
    int bid = blockIdx.x, tid = threadIdx.x;

    if (bid < PP) {
        // ---- prep: register-resident quantize + row stats + fused softmax ----
        int p = bid;
        const float4* src = (const float4*)(masks + (size_t)p * HWX);
        float m[16], s[16];
        float accn = 0.f, accs = 0.f, amax = 0.f;
#pragma unroll
        for (int j = 0; j < 4; ++j) {
            float4 v = src[tid * 4 + j];   // 16 consecutive elems per thread
            float mv[4] = {v.x, v.y, v.z, v.w};
#pragma unroll
            for (int k = 0; k < 4; ++k) {
                float x = mv[k];
                float am = fabsf(x);
                float e = __expf(-am);
                float r = __fdividef(1.f, 1.f + e);
                float sv = (x >= 0.f) ? r : e * r;
                accn -= (fmaxf(x, 0.f) + __logf(1.f + e));
                accs += sv;
                amax = fmaxf(amax, am);
                m[4 * j + k] = x;
                s[4 * j + k] = sv;
            }
        }
        float tn = block_reduce_sum(accn, red);
        __syncthreads();
        float ts = block_reduce_sum(accs, red);
        __syncthreads();
        float mx = block_reduce_max(amax, red);
        if (tid == 0) {
            float mxs = fmaxf(mx, 1e-20f);
            sbcast = mxs;
            g_snp[p] = tn; g_psum[p] = ts;
            g_scl[p] = mxs * (1.f / 16129.f);
        }
        __syncthreads();
        float scale = __fdividef(127.f, sbcast);
        uint4 o1, o2;
        {
            uint32_t w1[4], w2[4];
#pragma unroll
            for (int j = 0; j < 4; ++j) {
                w1[j] = pack4(q8(m[4*j] * scale), q8(m[4*j+1] * scale),
                              q8(m[4*j+2] * scale), q8(m[4*j+3] * scale));
                w2[j] = pack4(q8(s[4*j] * 127.f), q8(s[4*j+1] * 127.f),
                              q8(s[4*j+2] * 127.f), q8(s[4*j+3] * 127.f));
            }
            o1 = make_uint4(w1[0], w1[1], w1[2], w1[3]);
            o2 = make_uint4(w2[0], w2[1], w2[2], w2[3]);
        }
        ((uint4*)(g_A1q + (size_t)p * HWX))[tid] = o1;
        ((uint4*)(g_A2q + (size_t)p * HWX))[tid] = o2;

        // ---- fused softmax over NC=81 classes for this row ----
        float* sh = (float*)smr;
        float x = (tid < NC) ? logits[(size_t)p * NC + tid] : -1e30f;
        if (tid < 128) sh[tid] = x;
        __syncthreads();
        for (int st = 64; st > 0; st >>= 1) { if (tid < st) sh[tid] = fmaxf(sh[tid], sh[tid + st]); __syncthreads(); }
        float smx = sh[0]; __syncthreads();
        float e = (tid < NC) ? __expf(x - smx) : 0.f;
        if (tid < 128) sh[tid] = e;
        __syncthreads();
        for (int st = 64; st > 0; st >>= 1) { if (tid < st) sh[tid] += sh[tid + st]; __syncthreads(); }
        float inv = __fdividef(1.f, sh[0]);
        if (tid < NC) g_prob[(size_t)p * NC + tid] = e * inv;
    } else if (bid < PP + TT) {
        // ---- resize target masks 128->64 + row sums + int8 quantize ----
        int t = bid - PP;
        const float* src = tmasks + (size_t)t * HM * HM;
        float (*htmp)[HH] = (float(*)[HH])smr;
        for (int e = tid; e < HM * HH; e += 256) {
            int r = e >> 6, i = e & 63;
            int j0; float w[4]; taps64(i, j0, w);
            const float* row = src + r * HM;
            htmp[r][i] = w[0]*row[j0] + w[1]*row[j0+1] + w[2]*row[j0+2] + w[3]*row[j0+3];
        }
        __syncthreads();
        float lsum = 0.f;
        for (int e = tid; e < HWX; e += 256) {
            int o = e >> 6, i = e & 63;
            int j0; float w[4]; taps64(o, j0, w);
            float v = w[0]*htmp[j0][i] + w[1]*htmp[j0+1][i] + w[2]*htmp[j0+2][i] + w[3]*htmp[j0+3][i];
            g_tmq[(size_t)t * HWX + e] = (int8_t)q8(v * 127.f);
            lsum += v;
        }
        __syncthreads();
        float tot = block_reduce_sum(lsum, red);
        if (tid == 0) g_tsum[t] = tot;
    } else {
        // ---- label decode (robust to int32/int64) ----
        __shared__ int odd_nz;
        if (tid == 0) odd_nz = 0;
        __syncthreads();
        const int* li = (const int*)labels;
        for (int i = tid; i < TT / 2; i += 256)
            if (li[2 * i + 1] != 0) atomicOr(&odd_nz, 1);
        __syncthreads();
        bool is64 = (odd_nz == 0);
        for (int t = tid; t < TT; t += 256)
            g_lab[t] = is64 ? (int)((const long long*)labels)[t] : li[t];
    }
}

// ---------------- shared epilogue pieces --------------------------------------
struct TInfo {
    float cx, cy, w, h, x0, y0, x1, y1, area, tsum;
    int lab, pad;
};

__device__ __forceinline__ void fill_tinfo(TInfo* sT, int n0, const float* tboxes,
                                           int tid, int cnt) {
    for (int i = tid; i < cnt; i += blockDim.x) {
        int t = n0 + i;
        TInfo ti;
        if (t < TT) {
            float4 tb = *(const float4*)(tboxes + 4 * t);
            ti.cx = tb.x; ti.cy = tb.y; ti.w = tb.z; ti.h = tb.w;
            ti.x0 = tb.x - 0.5f * tb.z; ti.y0 = tb.y - 0.5f * tb.w;
            ti.x1 = tb.x + 0.5f * tb.z; ti.y1 = tb.y + 0.5f * tb.w;
            ti.area = tb.z * tb.w;
            ti.tsum = g_tsum[t];
            ti.lab = g_lab[t];
        } else {
            ti.cx = ti.cy = ti.w = ti.h = 0.f;
            ti.x0 = ti.y0 = ti.x1 = ti.y1 = 0.f;
            ti.area = ti.tsum = 0.f; ti.lab = 0;
        }
        ti.pad = 0;
        sT[i] = ti;
    }
}

__device__ __forceinline__ float cost_elem(
    float d1, float d2, const TInfo& ti, const float4& pb,
    float px0, float py0, float px1, float py1, float parea,
    float snp_p, float psum_p, const float* prow) {
    const float inv_hw = 1.0f / (float)HWX;
    float l1 = fabsf(pb.x - ti.cx) + fabsf(pb.y - ti.cy)
             + fabsf(pb.z - ti.w) + fabsf(pb.w - ti.h);
    float ix0 = fmaxf(px0, ti.x0), iy0 = fmaxf(py0, ti.y0);
    float ix1 = fminf(px1, ti.x1), iy1 = fminf(py1, ti.y1);
    float inter = fmaxf(ix1 - ix0, 0.f) * fmaxf(iy1 - iy0, 0.f);
    float uni = parea + ti.area - inter;
    float iou = inter / uni;
    float ex0 = fminf(px0, ti.x0), ey0 = fminf(py0, ti.y0);
    float ex1 = fmaxf(px1, ti.x1), ey1 = fmaxf(py1, ti.y1);
    float enc = fmaxf(ex1 - ex0, 0.f) * fmaxf(ey1 - ey0, 0.f);
    float giou = iou - (enc - uni) / enc;
    float cmask = -(d1 + snp_p) * inv_hw;
    float cdice = 1.f - (2.f * d2 + 1e-5f) / (psum_p + ti.tsum + 1e-5f);
    float ccls = -prow[ti.lab];
    return 5.f * l1 - 2.f * giou + 2.f * ccls + 5.f * cmask + 5.f * cdice;
}

// ---------------- GEMM: int8 TMA, 129 CTAs single wave, 14 warps ---------------
#define BM_T 112               // 43 m-tiles x 3 n-tiles = 129 CTAs <= 148 SMs
#define BN_T 160
#define NI 10                  // n8 frags per warp (warp tile 16x80)
#define BKS 128                // K elems per stage (128B rows of s8 -> SW128)
#define KTN (HWX / BKS)        // 32 stages
#define NSTG 4
#define MATBA (BM_T * 128)     // 14KB A tile (112 rows x 128B)
#define MATBB (BN_T * 128)     // 20KB B tile (160 rows x 128B)
#define STGB (2 * MATBA + MATBB)   // 48KB
#define NT_TMA 448             // 14 warps: 7 along M x 2 along N
#define DYN_SMEM (NSTG * STGB + 1024)

__global__ void __launch_bounds__(NT_TMA, 1) gemm_tma(
    const __grid_constant__ CUtensorMap tmA1,
    const __grid_constant__ CUtensorMap tmA2,
    const __grid_constant__ CUtensorMap tmB,
    const float* __restrict__ pboxes, const float* __restrict__ tboxes,
    float* __restrict__ out) {
    extern __shared__ char dsm[];
    __shared__ TInfo sT[BN_T];
    __shared__ __align__(8) unsigned long long smbar[NSTG];

    uint32_t dbase = (smem_u32(dsm) + 1023) & ~1023u;
    uint32_t mb = smem_u32(smbar);

    int tid = threadIdx.x, lane = tid & 31, warp = tid >> 5;
    int n0 = blockIdx.x * BN_T, m0 = blockIdx.y * BM_T;
    int nvalid = min(BN_T, TT - n0);
    int wm = warp % 7, wn = warp / 7;
    int wr = wm * 16;            // 7 warps along M (16 rows each)
    int wc = wn * (NI * 8);      // 2 warps along N (80 cols each)

    if (tid == 0)
        for (int s = 0; s < NSTG; ++s) MBARRIER_INIT(mb + 8 * s, 1);
    fill_tinfo(sT, n0, tboxes, tid, BN_T);
    __syncthreads();

    if (tid == 0) {
#pragma unroll
        for (int s = 0; s < 3; ++s) {
            uint32_t fb = mb + 8 * s;
            MBARRIER_EXPECT_TX(fb, STGB);
            uint32_t d = dbase + s * STGB;
            int x = s * BKS;
            tma2d(d,             &tmA1, x, m0, fb);
            tma2d(d + MATBA,     &tmA2, x, m0, fb);
            tma2d(d + 2 * MATBA, &tmB,  x, n0, fb);
        }
    }

    int acc[2][NI][4];   // [mat][ni][frag] s32, warp tile 16x80
#pragma unroll
    for (int a = 0; a < 2; ++a)
#pragma unroll
        for (int c = 0; c < NI; ++c)
#pragma unroll
            for (int d = 0; d < 4; ++d) acc[a][c][d] = 0;

    int a_row_l = (lane & 15);
    int a_coff  = (lane >> 4) * 16;          // bytes
    int b_row_l = (lane & 7) + ((lane >> 4) * 8);
    int b_coff  = ((lane >> 3) & 1) * 16;    // bytes

    uint32_t phases = 0;

    for (int kt = 0; kt < KTN; ++kt) {
        __syncthreads();   // all warps done reading slot (kt-1)&3
        if (tid == 0 && kt + 3 < KTN) {
            int sl = (kt + 3) & 3;
            uint32_t fb = mb + 8 * sl;
            MBARRIER_EXPECT_TX(fb, STGB);
            uint32_t d = dbase + sl * STGB;
            int x = (kt + 3) * BKS;
            tma2d(d,             &tmA1, x, m0, fb);
            tma2d(d + MATBA,     &tmA2, x, m0, fb);
            tma2d(d + 2 * MATBA, &tmB,  x, n0, fb);
        }
        int sl = kt & 3;
        MBARRIER_WAIT_PARITY(mb + 8 * sl, (phases >> sl) & 1);
        phases ^= 1u << sl;

        uint32_t sb = dbase + sl * STGB;
#pragma unroll
        for (int ks = 0; ks < 4; ++ks) {   // 4 x k32 per 128B stage row
            int cbyte = ks * 32;
            uint32_t af[2][4];
            {
                uint32_t off = (uint32_t)((wr + a_row_l) * 128 + cbyte + a_coff);
                uint32_t sw = SW128(off);
                ldsm_x4(af[0], sb + sw);
                ldsm_x4(af[1], sb + MATBA + sw);
            }
            uint32_t bf[NI][2];
#pragma unroll
            for (int nh = 0; nh < NI / 2; ++nh) {
                uint32_t regs[4];
                uint32_t off = (uint32_t)((wc + nh * 16 + b_row_l) * 128 + cbyte + b_coff);
                ldsm_x4(regs, sb + 2 * MATBA + SW128(off));
                bf[nh * 2][0] = regs[0]; bf[nh * 2][1] = regs[1];
                bf[nh * 2 + 1][0] = regs[2]; bf[nh * 2 + 1][1] = regs[3];
            }
#pragma unroll
            for (int s2 = 0; s2 < 2; ++s2)
#pragma unroll
                for (int ni = 0; ni < NI; ++ni)
                    mma_s8(acc[s2][ni], af[s2], bf[ni]);
        }
    }

    // ---- fused cost epilogue (warp tile 16x80, s32 -> float dequant) ----
    const float inv127sq = 1.f / 16129.f;
#pragma unroll
    for (int rh = 0; rh < 2; ++rh) {
        int p = m0 + wr + (lane >> 2) + rh * 8;
        if (p >= PP) continue;
        float snp_p = g_snp[p], psum_p = g_psum[p];
        float f1p = g_scl[p];
        float4 pb = *(const float4*)(pboxes + 4 * p);
        float px0 = pb.x - 0.5f * pb.z, py0 = pb.y - 0.5f * pb.w;
        float px1 = pb.x + 0.5f * pb.z, py1 = pb.y + 0.5f * pb.w;
        float parea = pb.z * pb.w;
        const float* prow = g_prob + (size_t)p * NC;
#pragma unroll
        for (int ni = 0; ni < NI; ++ni) {
            int tl0 = wc + ni * 8 + 2 * (lane & 3);
            if (tl0 >= nvalid) continue;
            float r2[2];
#pragma unroll
            for (int cc = 0; cc < 2; ++cc) {
                float d1 = (float)acc[0][ni][rh * 2 + cc] * f1p;
                float d2 = (float)acc[1][ni][rh * 2 + cc] * inv127sq;
                r2[cc] = cost_elem(d1, d2, sT[tl0 + cc], pb, px0, py0, px1, py1, parea,
                                   snp_p, psum_p, prow);
            }
            *(float2*)(out + (size_t)p * TT + n0 + tl0) = make_float2(r2[0], r2[1]);
        }
    }
}

// ---------------- GEMM path B: cp.async fallback (same layout/compute) ---------
__global__ void __launch_bounds__(NT_TMA, 1) gemm_cpasync(
    const float* __restrict__ pboxes, const float* __restrict__ tboxes,
    float* __restrict__ out) {
    extern __shared__ char dsm[];
    __shared__ TInfo sT[BN_T];

    uint32_t dbase = (smem_u32(dsm) + 1023) & ~1023u;
    char* dgen = (char*)dsm + (dbase - smem_u32(dsm));   // generic ptr matching dbase

    int tid = threadIdx.x, lane = tid & 31, warp = tid >> 5;
    int n0 = blockIdx.x * BN_T, m0 = blockIdx.y * BM_T;
    int nvalid = min(BN_T, TT - n0);
    int wm = warp % 7, wn = warp / 7;
    int wr = wm * 16;
    int wc = wn * (NI * 8);

    fill_tinfo(sT, n0, tboxes, tid, BN_T);

    int acc[2][NI][4];
#pragma unroll
    for (int a = 0; a < 2; ++a)
#pragma unroll
        for (int c = 0; c < NI; ++c)
#pragma unroll
            for (int d = 0; d < 4; ++d) acc[a][c][d] = 0;

    int a_row_l = (lane & 15);
    int a_coff  = (lane >> 4) * 16;
    int b_row_l = (lane & 7) + ((lane >> 4) * 8);
    int b_coff  = ((lane >> 3) & 1) * 16;

    auto loadStage = [&](int slot, int kt) {
        char* base = dgen + slot * STGB;
        int k0 = kt * BKS;
        for (int i = tid; i < 3072; i += NT_TMA) {
            int ch = i & 7;
            int r = i >> 3;
            int mat, row;
            if (r < BM_T)            { mat = 0; row = r; }
            else if (r < 2 * BM_T)   { mat = 1; row = r - BM_T; }
            else                     { mat = 2; row = r - 2 * BM_T; }
            char* dst = base + ((mat == 0) ? 0 : (mat == 1) ? MATBA : 2 * MATBA)
                      + SW128(row * 128 + ch * 16);
            const int8_t* src;
            bool v;
            if (mat < 2) {
                int p = m0 + row;
                v = p < PP;
                const int8_t* g = (mat == 0) ? g_A1q : g_A2q;
                src = g + ((size_t)(v ? p : 0) * HWX + k0 + ch * 16);
            } else {
                int t = n0 + row;
                v = t < TT;
                src = g_tmq + ((size_t)(v ? t : 0) * HWX + k0 + ch * 16);
            }
            cpa16(dst, src, v);
        }
        cpcommit();
    };

    loadStage(0, 0);
    loadStage(1, 1);
    loadStage(2, 2);

    for (int kt = 0; kt < KTN; ++kt) {
        asm volatile("cp.async.wait_group 2;" ::: "memory");
        __syncthreads();
        int kl = kt + NSTG - 1;
        if (kl < KTN) loadStage(kl & 3, kl);

        uint32_t sb = dbase + (kt & 3) * STGB;
#pragma unroll
        for (int ks = 0; ks < 4; ++ks) {
            int cbyte = ks * 32;
            uint32_t af[2][4];
            {
                uint32_t off = (uint32_t)((wr + a_row_l) * 128 + cbyte + a_coff);
                uint32_t sw = SW128(off);
                ldsm_x4(af[0], sb + sw);
                ldsm_x4(af[1], sb + MATBA + sw);
            }
            uint32_t bf[NI][2];
#pragma unroll
            for (int nh = 0; nh < NI / 2; ++nh) {
                uint32_t regs[4];
                uint32_t off = (uint32_t)((wc + nh * 16 + b_row_l) * 128 + cbyte + b_coff);
                ldsm_x4(regs, sb + 2 * MATBA + SW128(off));
                bf[nh * 2][0] = regs[0]; bf[nh * 2][1] = regs[1];
                bf[nh * 2 + 1][0] = regs[2]; bf[nh * 2 + 1][1] = regs[3];
            }
#pragma unroll
            for (int s2 = 0; s2 < 2; ++s2)
#pragma unroll
                for (int ni = 0; ni < NI; ++ni)
                    mma_s8(acc[s2][ni], af[s2], bf[ni]);
        }
    }

    const float inv127sq = 1.f / 16129.f;
#pragma unroll
    for (int rh = 0; rh < 2; ++rh) {
        int p = m0 + wr + (lane >> 2) + rh * 8;
        if (p >= PP) continue;
        float snp_p = g_snp[p], psum_p = g_psum[p];
        float f1p = g_scl[p];
        float4 pb = *(const float4*)(pboxes + 4 * p);
        float px0 = pb.x - 0.5f * pb.z, py0 = pb.y - 0.5f * pb.w;
        float px1 = pb.x + 0.5f * pb.z, py1 = pb.y + 0.5f * pb.w;
        float parea = pb.z * pb.w;
        const float* prow = g_prob + (size_t)p * NC;
#pragma unroll
        for (int ni = 0; ni < NI; ++ni) {
            int tl0 = wc + ni * 8 + 2 * (lane & 3);
            if (tl0 >= nvalid) continue;
            float r2[2];
#pragma unroll
            for (int cc = 0; cc < 2; ++cc) {
                float d1 = (float)acc[0][ni][rh * 2 + cc] * f1p;
                float d2 = (float)acc[1][ni][rh * 2 + cc] * inv127sq;
                r2[cc] = cost_elem(d1, d2, sT[tl0 + cc], pb, px0, py0, px1, py1, parea,
                                   snp_p, psum_p, prow);
            }
            *(float2*)(out + (size_t)p * TT + n0 + tl0) = make_float2(r2[0], r2[1]);
        }
    }
}

// ---------------- host: tensormap encoding + launch ---------------------------
typedef CUresult (*PFN_encodeTiled)(
    CUtensorMap*, CUtensorMapDataType, cuuint32_t, void*,
    const cuuint64_t*, const cuuint64_t*, const cuuint32_t*, const cuuint32_t*,
    CUtensorMapInterleave, CUtensorMapSwizzle, CUtensorMapL2promotion,
    CUtensorMapFloatOOBfill);

static CUresult encode_map(PFN_encodeTiled enc, CUtensorMap* tm, void* ptr,
                           unsigned long long rows, unsigned box_rows) {
    cuuint64_t dims[2]    = {(cuuint64_t)HWX, (cuuint64_t)rows};
    cuuint64_t strides[1] = {(cuuint64_t)HWX};          // bytes (int8)
    cuuint32_t box[2]     = {BKS, box_rows};            // 128 x rows
    cuuint32_t estr[2]    = {1, 1};
    return enc(tm, CU_TENSOR_MAP_DATA_TYPE_UINT8, 2, ptr, dims, strides, box, estr,
               CU_TENSOR_MAP_INTERLEAVE_NONE, CU_TENSOR_MAP_SWIZZLE_128B,
               CU_TENSOR_MAP_L2_PROMOTION_L2_128B, CU_TENSOR_MAP_FLOAT_OOB_FILL_NONE);
}

extern "C" void kernel_launch(void* const* d_in, const int* in_sizes, int n_in,
                              void* d_out, int out_size) {
    const float* pred_logits = (const float*)d_in[0];
    const float* pred_boxes  = (const float*)d_in[1];
    const float* pred_masks  = (const float*)d_in[2];
    const float* tgt_boxes   = (const float*)d_in[3];
    const float* tgt_masks   = (const float*)d_in[4];
    const void*  tgt_labels  = (const void*)d_in[5];
    float* out = (float*)d_out;

    aux_kernel<<<PP + TT + 1, 256>>>(pred_logits, pred_masks, tgt_masks, tgt_labels);

    // Try the TMA path; verified fallback to cp.async path.
    bool tma_ok = false;
    alignas(64) CUtensorMap tmA1, tmA2, tmB;
    void* fp = nullptr;
#if CUDART_VERSION >= 12000
    cudaDriverEntryPointQueryResult qr;
    cudaError_t e0 = cudaGetDriverEntryPoint("cuTensorMapEncodeTiled", &fp,
                                             cudaEnableDefault, &qr);
#else
    cudaError_t e0 = cudaGetDriverEntryPoint("cuTensorMapEncodeTiled", &fp,
                                             cudaEnableDefault);
#endif
    if (e0 == cudaSuccess && fp != nullptr) {
        PFN_encodeTiled enc = (PFN_encodeTiled)fp;
        void *pa1 = nullptr, *pa2 = nullptr, *pb = nullptr;
        cudaError_t s1 = cudaGetSymbolAddress(&pa1, g_A1q);
        cudaError_t s2 = cudaGetSymbolAddress(&pa2, g_A2q);
        cudaError_t s3 = cudaGetSymbolAddress(&pb,  g_tmq);
        if (s1 == cudaSuccess && s2 == cudaSuccess && s3 == cudaSuccess) {
            CUresult r1 = encode_map(enc, &tmA1, pa1, PP, BM_T);
            CUresult r2 = encode_map(enc, &tmA2, pa2, PP, BM_T);
            CUresult r3 = encode_map(enc, &tmB,  pb,  TT, BN_T);
            tma_ok = (r1 == CUDA_SUCCESS && r2 == CUDA_SUCCESS && r3 == CUDA_SUCCESS);
        }
    }

    dim3 grid((TT + BN_T - 1) / BN_T, (PP + BM_T - 1) / BM_T);   // 3 x 43 = 129
    if (tma_ok) {
        cudaFuncSetAttribute(gemm_tma, cudaFuncAttributeMaxDynamicSharedMemorySize, DYN_SMEM);
        gemm_tma<<<grid, NT_TMA, DYN_SMEM>>>(tmA1, tmA2, tmB, pred_boxes, tgt_boxes, out);
    } else {
        cudaFuncSetAttribute(gemm_cpasync, cudaFuncAttributeMaxDynamicSharedMemorySize, DYN_SMEM);
        gemm_cpasync<<<grid, NT_TMA, DYN_SMEM>>>(pred_boxes, tgt_boxes, out);
    }
}

// round 17
// speedup vs baseline: 2.1825x; 1.0549x over previous
#include <cuda_runtime.h>
#include <cuda.h>
#include <cuda_bf16.h>
#include <cstdint>
#include <math.h>

// Problem dims (fixed by the dataset)
#define BSZ 16
#define QQ  300
#define NC  81
#define HH  64
#define WWD 64
#define TT  400
#define HM  128
#define PP  (BSZ*QQ)     // 4800
#define HWX (HH*WWD)     // 4096

// ---------------- scratch (device globals; no allocation allowed) -------------
__device__ __align__(1024) int8_t g_A1q[(size_t)PP*HWX];   // quantized logits
__device__ __align__(1024) int8_t g_A2q[(size_t)PP*HWX];   // quantized sigmoid
__device__ __align__(1024) int8_t g_tmq[(size_t)TT*HWX];   // quantized resized targets
__device__ float g_tsum[TT];
__device__ float g_snp[PP];     // sum log_sigmoid(-m)
__device__ float g_psum[PP];    // sum sigmoid(m)
__device__ float g_scl[PP];     // maxm/(127*127) dequant factor for d1
__device__ float g_prob[(size_t)PP*NC];
__device__ int   g_lab[TT];     // decoded labels

// ---------------- small helpers -----------------------------------------------
__device__ __forceinline__ float block_reduce_sum(float v, float* sh) {
    int lane = threadIdx.x & 31, w = threadIdx.x >> 5;
#pragma unroll
    for (int o = 16; o; o >>= 1) v += __shfl_down_sync(0xffffffffu, v, o);
    if (lane == 0) sh[w] = v;
    __syncthreads();
    if (w == 0) {
        v = (lane < 8) ? sh[lane] : 0.f;
#pragma unroll
        for (int o = 4; o; o >>= 1) v += __shfl_down_sync(0xffffffffu, v, o);
    }
    return v;  // valid on thread 0
}

__device__ __forceinline__ void taps64(int i, int& j0, float w[4]) {
    if (i == 0)       { j0 = 0;   w[0] = 3.f/7.f; w[1] = 3.f/7.f; w[2] = 1.f/7.f; w[3] = 0.f; }
    else if (i == 63) { j0 = 124; w[0] = 0.f;     w[1] = 1.f/7.f; w[2] = 3.f/7.f; w[3] = 3.f/7.f; }
    else              { j0 = 2*i - 1; w[0] = 0.125f; w[1] = 0.375f; w[2] = 0.375f; w[3] = 0.125f; }
}

__device__ __forceinline__ uint32_t smem_u32(const void* p) {
    uint32_t a;
    asm("{ .reg .u64 t; cvta.to.shared.u64 t, %1; cvt.u32.u64 %0, t; }" : "=r"(a) : "l"(p));
    return a;
}

#define SW128(off) ((off) ^ (((off) >> 3) & 0x70))

__device__ __forceinline__ void cpa16(void* dst, const void* src, bool v) {
    uint32_t d = (uint32_t)__cvta_generic_to_shared(dst);
    int n = v ? 16 : 0;
    asm volatile("cp.async.cg.shared.global [%0], [%1], 16, %2;\n" :: "r"(d), "l"(src), "r"(n));
}
__device__ __forceinline__ void cpcommit() { asm volatile("cp.async.commit_group;\n"); }

// int8 MMA: m16n8k32 s8*s8 -> s32 (exact accumulation)
__device__ __forceinline__ void mma_s8(int c[4], const uint32_t a[4], const uint32_t b[2]) {
    asm volatile(
        "mma.sync.aligned.m16n8k32.row.col.s32.s8.s8.s32 "
        "{%0,%1,%2,%3}, {%4,%5,%6,%7}, {%8,%9}, {%0,%1,%2,%3};\n"
        : "+r"(c[0]), "+r"(c[1]), "+r"(c[2]), "+r"(c[3])
        : "r"(a[0]), "r"(a[1]), "r"(a[2]), "r"(a[3]), "r"(b[0]), "r"(b[1]));
}

__device__ __forceinline__ void ldsm_x4(uint32_t r[4], uint32_t addr) {
    asm volatile("ldmatrix.sync.aligned.m8n8.x4.shared.b16 {%0,%1,%2,%3}, [%4];"
        : "=r"(r[0]), "=r"(r[1]), "=r"(r[2]), "=r"(r[3]) : "r"(addr));
}

#define MBARRIER_INIT(addr, cnt) \
    asm volatile("mbarrier.init.shared.b64 [%0], %1;" :: "r"((uint32_t)(addr)), "r"((uint32_t)(cnt)) : "memory")

#define MBARRIER_EXPECT_TX(addr, tx) \
    asm volatile("mbarrier.arrive.expect_tx.shared.b64 _, [%0], %1;" :: "r"((uint32_t)(addr)), "r"((uint32_t)(tx)) : "memory")

#define MBARRIER_WAIT_PARITY(mbar_smem_addr, phase_parity) do { \
    uint32_t _mbar = (uint32_t)(mbar_smem_addr); \
    uint32_t _parity = (uint32_t)(phase_parity); \
    uint32_t _done; \
    asm volatile( \
        "{\n\t.reg .pred p;\n\t" \
        "mbarrier.try_wait.parity.acquire.cta.shared::cta.b64 p, [%1], %2;\n\t" \
        "selp.b32 %0, 1, 0, p;\n\t}" \
        : "=r"(_done) : "r"(_mbar), "r"(_parity) : "memory"); \
    if (!_done) { \
        asm volatile( \
            "{\n\t.reg .pred P1;\n\t" \
            "WAIT_LOOP_%=:\n\t" \
            "mbarrier.try_wait.parity.acquire.cta.shared::cta.b64 P1, [%0], %1, 0x989680;\n\t" \
            "@P1 bra.uni WAIT_DONE_%=;\n\t" \
            "bra.uni WAIT_LOOP_%=;\n\t" \
            "WAIT_DONE_%=:\n\t}" \
            :: "r"(_mbar), "r"(_parity) : "memory"); \
    } \
} while (0)

__device__ __forceinline__ void tma2d(uint32_t dst, const CUtensorMap* tmap,
                                      int x, int y, uint32_t mbar) {
    asm volatile(
        "cp.async.bulk.tensor.2d.shared::cta.global.tile.mbarrier::complete_tx::bytes "
        "[%0], [%1, {%2, %3}], [%4];"
        :: "r"(dst), "l"(tmap), "r"(x), "r"(y), "r"(mbar) : "memory");
}

__device__ __forceinline__ int q8(float x) {
    int q = __float2int_rn(x);
    return max(-127, min(127, q));
}
__device__ __forceinline__ uint32_t pack4(int a, int b, int c, int d) {
    return (uint32_t)(a & 0xff) | ((uint32_t)(b & 0xff) << 8)
         | ((uint32_t)(c & 0xff) << 16) | ((uint32_t)(d & 0xff) << 24);
}

// ---------------- fused aux kernel (prep+softmax | resize | label) ------------
__global__ void __launch_bounds__(256) aux_kernel(
    const float* __restrict__ logits, const float* __restrict__ masks,
    const float* __restrict__ tmasks, const void* __restrict__ labels) {
    __shared__ __align__(16) char smr[HM * HH * 4];   // 32KB (resize branch only)
    __shared__ float red3[24];     // 8 warps x 3 values
    __shared__ float sb3[3];       // broadcast: maxm, (unused), (unused)
    int bid = blockIdx.x, tid = threadIdx.x;
    int lane = tid & 31, warp = tid >> 5;

    if (bid < PP) {
        // ---- prep: register-resident quantize + row stats + fused softmax ----
        int p = bid;
        const float4* src = (const float4*)(masks + (size_t)p * HWX);
        float m[16], s[16];
        float accn = 0.f, accs = 0.f, amax = 0.f;
#pragma unroll
        for (int j = 0; j < 4; ++j) {
            float4 v = __ldcs(&src[tid * 4 + j]);   // streaming: evict-first
            float mv[4] = {v.x, v.y, v.z, v.w};
#pragma unroll
            for (int k = 0; k < 4; ++k) {
                float x = mv[k];
                float am = fabsf(x);
                float e = __expf(-am);
                float r = __fdividef(1.f, 1.f + e);
                float sv = (x >= 0.f) ? r : e * r;
                accn -= (fmaxf(x, 0.f) + __logf(1.f + e));
                accs += sv;
                amax = fmaxf(amax, am);
                m[4 * j + k] = x;
                s[4 * j + k] = sv;
            }
        }
        // fused triple reduction: (sum, sum, max) in one pass, one barrier round
#pragma unroll
        for (int o = 16; o; o >>= 1) {
            accn += __shfl_down_sync(0xffffffffu, accn, o);
            accs += __shfl_down_sync(0xffffffffu, accs, o);
            amax = fmaxf(amax, __shfl_down_sync(0xffffffffu, amax, o));
        }
        if (lane == 0) {
            red3[warp * 3 + 0] = accn;
            red3[warp * 3 + 1] = accs;
            red3[warp * 3 + 2] = amax;
        }
        __syncthreads();
        if (warp == 0) {
            float rn = (lane < 8) ? red3[lane * 3 + 0] : 0.f;
            float rs = (lane < 8) ? red3[lane * 3 + 1] : 0.f;
            float rm = (lane < 8) ? red3[lane * 3 + 2] : 0.f;
#pragma unroll
            for (int o = 4; o; o >>= 1) {
                rn += __shfl_down_sync(0xffffffffu, rn, o);
                rs += __shfl_down_sync(0xffffffffu, rs, o);
                rm = fmaxf(rm, __shfl_down_sync(0xffffffffu, rm, o));
            }
            if (lane == 0) {
                float mxs = fmaxf(rm, 1e-20f);
                sb3[0] = mxs;
                g_snp[p] = rn; g_psum[p] = rs;
                g_scl[p] = mxs * (1.f / 16129.f);
            }
        }
        __syncthreads();
        float scale = __fdividef(127.f, sb3[0]);
        {
            uint32_t w1[4], w2[4];
#pragma unroll
            for (int j = 0; j < 4; ++j) {
                w1[j] = pack4(q8(m[4*j] * scale), q8(m[4*j+1] * scale),
                              q8(m[4*j+2] * scale), q8(m[4*j+3] * scale));
                w2[j] = pack4(q8(s[4*j] * 127.f), q8(s[4*j+1] * 127.f),
                              q8(s[4*j+2] * 127.f), q8(s[4*j+3] * 127.f));
            }
            __stcs((uint4*)(g_A1q + (size_t)p * HWX) + tid,
                   make_uint4(w1[0], w1[1], w1[2], w1[3]));
            __stcs((uint4*)(g_A2q + (size_t)p * HWX) + tid,
                   make_uint4(w2[0], w2[1], w2[2], w2[3]));
        }

        // ---- softmax over NC=81 via warp shuffles (3 warps, 2 barriers) ----
        float* shf = (float*)smr;
        float x = (tid < NC) ? logits[(size_t)p * NC + tid] : -1e30f;
        if (warp < 3) {
            float wm = x;
#pragma unroll
            for (int o = 16; o; o >>= 1) wm = fmaxf(wm, __shfl_down_sync(0xffffffffu, wm, o));
            if (lane == 0) shf[warp] = wm;
        }
        __syncthreads();
        float smx = fmaxf(fmaxf(shf[0], shf[1]), shf[2]);
        float e = (tid < NC) ? __expf(x - smx) : 0.f;
        if (warp < 3) {
            float ws = e;
#pragma unroll
            for (int o = 16; o; o >>= 1) ws += __shfl_down_sync(0xffffffffu, ws, o);
            if (lane == 0) shf[4 + warp] = ws;
        }
        __syncthreads();
        float inv = __fdividef(1.f, shf[4] + shf[5] + shf[6]);
        if (tid < NC) g_prob[(size_t)p * NC + tid] = e * inv;
    } else if (bid < PP + TT) {
        // ---- resize target masks 128->64 + row sums + int8 quantize ----
        int t = bid - PP;
        const float* src = tmasks + (size_t)t * HM * HM;
        float (*htmp)[HH] = (float(*)[HH])smr;
        for (int e = tid; e < HM * HH; e += 256) {
            int r = e >> 6, i = e & 63;
            int j0; float w[4]; taps64(i, j0, w);
            const float* row = src + r * HM;
            htmp[r][i] = w[0]*__ldcs(row+j0) + w[1]*__ldcs(row+j0+1)
                       + w[2]*__ldcs(row+j0+2) + w[3]*__ldcs(row+j0+3);
        }
        __syncthreads();
        float lsum = 0.f;
        for (int e = tid; e < HWX; e += 256) {
            int o = e >> 6, i = e & 63;
            int j0; float w[4]; taps64(o, j0, w);
            float v = w[0]*htmp[j0][i] + w[1]*htmp[j0+1][i] + w[2]*htmp[j0+2][i] + w[3]*htmp[j0+3][i];
            g_tmq[(size_t)t * HWX + e] = (int8_t)q8(v * 127.f);
            lsum += v;
        }
        __syncthreads();
        float tot = block_reduce_sum(lsum, red3);
        if (tid == 0) g_tsum[t] = tot;
    } else {
        // ---- label decode (robust to int32/int64) ----
        __shared__ int odd_nz;
        if (tid == 0) odd_nz = 0;
        __syncthreads();
        const int* li = (const int*)labels;
        for (int i = tid; i < TT / 2; i += 256)
            if (li[2 * i + 1] != 0) atomicOr(&odd_nz, 1);
        __syncthreads();
        bool is64 = (odd_nz == 0);
        for (int t = tid; t < TT; t += 256)
            g_lab[t] = is64 ? (int)((const long long*)labels)[t] : li[t];
    }
}

// ---------------- shared epilogue pieces --------------------------------------
struct TInfo {
    float cx, cy, w, h, x0, y0, x1, y1, area, tsum;
    int lab, pad;
};

__device__ __forceinline__ void fill_tinfo(TInfo* sT, int n0, const float* tboxes,
                                           int tid, int cnt) {
    for (int i = tid; i < cnt; i += blockDim.x) {
        int t = n0 + i;
        TInfo ti;
        if (t < TT) {
            float4 tb = *(const float4*)(tboxes + 4 * t);
            ti.cx = tb.x; ti.cy = tb.y; ti.w = tb.z; ti.h = tb.w;
            ti.x0 = tb.x - 0.5f * tb.z; ti.y0 = tb.y - 0.5f * tb.w;
            ti.x1 = tb.x + 0.5f * tb.z; ti.y1 = tb.y + 0.5f * tb.w;
            ti.area = tb.z * tb.w;
            ti.tsum = g_tsum[t];
            ti.lab = g_lab[t];
        } else {
            ti.cx = ti.cy = ti.w = ti.h = 0.f;
            ti.x0 = ti.y0 = ti.x1 = ti.y1 = 0.f;
            ti.area = ti.tsum = 0.f; ti.lab = 0;
        }
        ti.pad = 0;
        sT[i] = ti;
    }
}

__device__ __forceinline__ float cost_elem(
    float d1, float d2, const TInfo& ti, const float4& pb,
    float px0, float py0, float px1, float py1, float parea,
    float snp_p, float psum_p, const float* prow) {
    const float inv_hw = 1.0f / (float)HWX;
    float l1 = fabsf(pb.x - ti.cx) + fabsf(pb.y - ti.cy)
             + fabsf(pb.z - ti.w) + fabsf(pb.w - ti.h);
    float ix0 = fmaxf(px0, ti.x0), iy0 = fmaxf(py0, ti.y0);
    float ix1 = fminf(px1, ti.x1), iy1 = fminf(py1, ti.y1);
    float inter = fmaxf(ix1 - ix0, 0.f) * fmaxf(iy1 - iy0, 0.f);
    float uni = parea + ti.area - inter;
    float iou = inter / uni;
    float ex0 = fminf(px0, ti.x0), ey0 = fminf(py0, ti.y0);
    float ex1 = fmaxf(px1, ti.x1), ey1 = fmaxf(py1, ti.y1);
    float enc = fmaxf(ex1 - ex0, 0.f) * fmaxf(ey1 - ey0, 0.f);
    float giou = iou - (enc - uni) / enc;
    float cmask = -(d1 + snp_p) * inv_hw;
    float cdice = 1.f - (2.f * d2 + 1e-5f) / (psum_p + ti.tsum + 1e-5f);
    float ccls = -prow[ti.lab];
    return 5.f * l1 - 2.f * giou + 2.f * ccls + 5.f * cmask + 5.f * cdice;
}

// ---------------- GEMM: int8 TMA, 129 CTAs single wave, 14 warps ---------------
#define BM_T 112               // 43 m-tiles x 3 n-tiles = 129 CTAs <= 148 SMs
#define BN_T 160
#define NI 10                  // n8 frags per warp (warp tile 16x80)
#define BKS 128                // K elems per stage (128B rows of s8 -> SW128)
#define KTN (HWX / BKS)        // 32 stages
#define NSTG 4
#define MATBA (BM_T * 128)     // 14KB A tile (112 rows x 128B)
#define MATBB (BN_T * 128)     // 20KB B tile (160 rows x 128B)
#define STGB (2 * MATBA + MATBB)   // 48KB
#define NT_TMA 448             // 14 warps: 7 along M x 2 along N
#define DYN_SMEM (NSTG * STGB + 1024)

__global__ void __launch_bounds__(NT_TMA, 1) gemm_tma(
    const __grid_constant__ CUtensorMap tmA1,
    const __grid_constant__ CUtensorMap tmA2,
    const __grid_constant__ CUtensorMap tmB,
    const float* __restrict__ pboxes, const float* __restrict__ tboxes,
    float* __restrict__ out) {
    extern __shared__ char dsm[];
    __shared__ TInfo sT[BN_T];
    __shared__ __align__(8) unsigned long long smbar[NSTG];

    uint32_t dbase = (smem_u32(dsm) + 1023) & ~1023u;
    uint32_t mb = smem_u32(smbar);

    int tid = threadIdx.x, lane = tid & 31, warp = tid >> 5;
    int n0 = blockIdx.x * BN_T, m0 = blockIdx.y * BM_T;
    int nvalid = min(BN_T, TT - n0);
    int wm = warp % 7, wn = warp / 7;
    int wr = wm * 16;            // 7 warps along M (16 rows each)
    int wc = wn * (NI * 8);      // 2 warps along N (80 cols each)

    if (tid == 0)
        for (int s = 0; s < NSTG; ++s) MBARRIER_INIT(mb + 8 * s, 1);
    fill_tinfo(sT, n0, tboxes, tid, BN_T);
    __syncthreads();

    if (tid == 0) {
#pragma unroll
        for (int s = 0; s < 3; ++s) {
            uint32_t fb = mb + 8 * s;
            MBARRIER_EXPECT_TX(fb, STGB);
            uint32_t d = dbase + s * STGB;
            int x = s * BKS;
            tma2d(d,             &tmA1, x, m0, fb);
            tma2d(d + MATBA,     &tmA2, x, m0, fb);
            tma2d(d + 2 * MATBA, &tmB,  x, n0, fb);
        }
    }

    int acc[2][NI][4];   // [mat][ni][frag] s32, warp tile 16x80
#pragma unroll
    for (int a = 0; a < 2; ++a)
#pragma unroll
        for (int c = 0; c < NI; ++c)
#pragma unroll
            for (int d = 0; d < 4; ++d) acc[a][c][d] = 0;

    int a_row_l = (lane & 15);
    int a_coff  = (lane >> 4) * 16;          // bytes
    int b_row_l = (lane & 7) + ((lane >> 4) * 8);
    int b_coff  = ((lane >> 3) & 1) * 16;    // bytes

    uint32_t phases = 0;

    for (int kt = 0; kt < KTN; ++kt) {
        __syncthreads();   // all warps done reading slot (kt-1)&3
        if (tid == 0 && kt + 3 < KTN) {
            int sl = (kt + 3) & 3;
            uint32_t fb = mb + 8 * sl;
            MBARRIER_EXPECT_TX(fb, STGB);
            uint32_t d = dbase + sl * STGB;
            int x = (kt + 3) * BKS;
            tma2d(d,             &tmA1, x, m0, fb);
            tma2d(d + MATBA,     &tmA2, x, m0, fb);
            tma2d(d + 2 * MATBA, &tmB,  x, n0, fb);
        }
        int sl = kt & 3;
        MBARRIER_WAIT_PARITY(mb + 8 * sl, (phases >> sl) & 1);
        phases ^= 1u << sl;

        uint32_t sb = dbase + sl * STGB;
#pragma unroll
        for (int ks = 0; ks < 4; ++ks) {   // 4 x k32 per 128B stage row
            int cbyte = ks * 32;
            uint32_t af[2][4];
            {
                uint32_t off = (uint32_t)((wr + a_row_l) * 128 + cbyte + a_coff);
                uint32_t sw = SW128(off);
                ldsm_x4(af[0], sb + sw);
                ldsm_x4(af[1], sb + MATBA + sw);
            }
            uint32_t bf[NI][2];
#pragma unroll
            for (int nh = 0; nh < NI / 2; ++nh) {
                uint32_t regs[4];
                uint32_t off = (uint32_t)((wc + nh * 16 + b_row_l) * 128 + cbyte + b_coff);
                ldsm_x4(regs, sb + 2 * MATBA + SW128(off));
                bf[nh * 2][0] = regs[0]; bf[nh * 2][1] = regs[1];
                bf[nh * 2 + 1][0] = regs[2]; bf[nh * 2 + 1][1] = regs[3];
            }
#pragma unroll
            for (int s2 = 0; s2 < 2; ++s2)
#pragma unroll
                for (int ni = 0; ni < NI; ++ni)
                    mma_s8(acc[s2][ni], af[s2], bf[ni]);
        }
    }

    // ---- fused cost epilogue (warp tile 16x80, s32 -> float dequant) ----
    const float inv127sq = 1.f / 16129.f;
#pragma unroll
    for (int rh = 0; rh < 2; ++rh) {
        int p = m0 + wr + (lane >> 2) + rh * 8;
        if (p >= PP) continue;
        float snp_p = g_snp[p], psum_p = g_psum[p];
        float f1p = g_scl[p];
        float4 pb = *(const float4*)(pboxes + 4 * p);
        float px0 = pb.x - 0.5f * pb.z, py0 = pb.y - 0.5f * pb.w;
        float px1 = pb.x + 0.5f * pb.z, py1 = pb.y + 0.5f * pb.w;
        float parea = pb.z * pb.w;
        const float* prow = g_prob + (size_t)p * NC;
#pragma unroll
        for (int ni = 0; ni < NI; ++ni) {
            int tl0 = wc + ni * 8 + 2 * (lane & 3);
            if (tl0 >= nvalid) continue;
            float r2[2];
#pragma unroll
            for (int cc = 0; cc < 2; ++cc) {
                float d1 = (float)acc[0][ni][rh * 2 + cc] * f1p;
                float d2 = (float)acc[1][ni][rh * 2 + cc] * inv127sq;
                r2[cc] = cost_elem(d1, d2, sT[tl0 + cc], pb, px0, py0, px1, py1, parea,
                                   snp_p, psum_p, prow);
            }
            *(float2*)(out + (size_t)p * TT + n0 + tl0) = make_float2(r2[0], r2[1]);
        }
    }
}

// ---------------- GEMM path B: cp.async fallback (same layout/compute) ---------
__global__ void __launch_bounds__(NT_TMA, 1) gemm_cpasync(
    const float* __restrict__ pboxes, const float* __restrict__ tboxes,
    float* __restrict__ out) {
    extern __shared__ char dsm[];
    __shared__ TInfo sT[BN_T];

    uint32_t dbase = (smem_u32(dsm) + 1023) & ~1023u;
    char* dgen = (char*)dsm + (dbase - smem_u32(dsm));   // generic ptr matching dbase

    int tid = threadIdx.x, lane = tid & 31, warp = tid >> 5;
    int n0 = blockIdx.x * BN_T, m0 = blockIdx.y * BM_T;
    int nvalid = min(BN_T, TT - n0);
    int wm = warp % 7, wn = warp / 7;
    int wr = wm * 16;
    int wc = wn * (NI * 8);

    fill_tinfo(sT, n0, tboxes, tid, BN_T);

    int acc[2][NI][4];
#pragma unroll
    for (int a = 0; a < 2; ++a)
#pragma unroll
        for (int c = 0; c < NI; ++c)
#pragma unroll
            for (int d = 0; d < 4; ++d) acc[a][c][d] = 0;

    int a_row_l = (lane & 15);
    int a_coff  = (lane >> 4) * 16;
    int b_row_l = (lane & 7) + ((lane >> 4) * 8);
    int b_coff  = ((lane >> 3) & 1) * 16;

    auto loadStage = [&](int slot, int kt) {
        char* base = dgen + slot * STGB;
        int k0 = kt * BKS;
        for (int i = tid; i < 3072; i += NT_TMA) {
            int ch = i & 7;
            int r = i >> 3;
            int mat, row;
            if (r < BM_T)            { mat = 0; row = r; }
            else if (r < 2 * BM_T)   { mat = 1; row = r - BM_T; }
            else                     { mat = 2; row = r - 2 * BM_T; }
            char* dst = base + ((mat == 0) ? 0 : (mat == 1) ? MATBA : 2 * MATBA)
                      + SW128(row * 128 + ch * 16);
            const int8_t* src;
            bool v;
            if (mat < 2) {
                int p = m0 + row;
                v = p < PP;
                const int8_t* g = (mat == 0) ? g_A1q : g_A2q;
                src = g + ((size_t)(v ? p : 0) * HWX + k0 + ch * 16);
            } else {
                int t = n0 + row;
                v = t < TT;
                src = g_tmq + ((size_t)(v ? t : 0) * HWX + k0 + ch * 16);
            }
            cpa16(dst, src, v);
        }
        cpcommit();
    };

    loadStage(0, 0);
    loadStage(1, 1);
    loadStage(2, 2);

    for (int kt = 0; kt < KTN; ++kt) {
        asm volatile("cp.async.wait_group 2;" ::: "memory");
        __syncthreads();
        int kl = kt + NSTG - 1;
        if (kl < KTN) loadStage(kl & 3, kl);

        uint32_t sb = dbase + (kt & 3) * STGB;
#pragma unroll
        for (int ks = 0; ks < 4; ++ks) {
            int cbyte = ks * 32;
            uint32_t af[2][4];
            {
                uint32_t off = (uint32_t)((wr + a_row_l) * 128 + cbyte + a_coff);
                uint32_t sw = SW128(off);
                ldsm_x4(af[0], sb + sw);
                ldsm_x4(af[1], sb + MATBA + sw);
            }
            uint32_t bf[NI][2];
#pragma unroll
            for (int nh = 0; nh < NI / 2; ++nh) {
                uint32_t regs[4];
                uint32_t off = (uint32_t)((wc + nh * 16 + b_row_l) * 128 + cbyte + b_coff);
                ldsm_x4(regs, sb + 2 * MATBA + SW128(off));
                bf[nh * 2][0] = regs[0]; bf[nh * 2][1] = regs[1];
                bf[nh * 2 + 1][0] = regs[2]; bf[nh * 2 + 1][1] = regs[3];
            }
#pragma unroll
            for (int s2 = 0; s2 < 2; ++s2)
#pragma unroll
                for (int ni = 0; ni < NI; ++ni)
                    mma_s8(acc[s2][ni], af[s2], bf[ni]);
        }
    }

    const float inv127sq = 1.f / 16129.f;
#pragma unroll
    for (int rh = 0; rh < 2; ++rh) {
        int p = m0 + wr + (lane >> 2) + rh * 8;
        if (p >= PP) continue;
        float snp_p = g_snp[p], psum_p = g_psum[p];
        float f1p = g_scl[p];
        float4 pb = *(const float4*)(pboxes + 4 * p);
        float px0 = pb.x - 0.5f * pb.z, py0 = pb.y - 0.5f * pb.w;
        float px1 = pb.x + 0.5f * pb.z, py1 = pb.y + 0.5f * pb.w;
        float parea = pb.z * pb.w;
        const float* prow = g_prob + (size_t)p * NC;
#pragma unroll
        for (int ni = 0; ni < NI; ++ni) {
            int tl0 = wc + ni * 8 + 2 * (lane & 3);
            if (tl0 >= nvalid) continue;
            float r2[2];
#pragma unroll
            for (int cc = 0; cc < 2; ++cc) {
                float d1 = (float)acc[0][ni][rh * 2 + cc] * f1p;
                float d2 = (float)acc[1][ni][rh * 2 + cc] * inv127sq;
                r2[cc] = cost_elem(d1, d2, sT[tl0 + cc], pb, px0, py0, px1, py1, parea,
                                   snp_p, psum_p, prow);
            }
            *(float2*)(out + (size_t)p * TT + n0 + tl0) = make_float2(r2[0], r2[1]);
        }
    }
}

// ---------------- host: tensormap encoding + launch ---------------------------
typedef CUresult (*PFN_encodeTiled)(
    CUtensorMap*, CUtensorMapDataType, cuuint32_t, void*,
    const cuuint64_t*, const cuuint64_t*, const cuuint32_t*, const cuuint32_t*,
    CUtensorMapInterleave, CUtensorMapSwizzle, CUtensorMapL2promotion,
    CUtensorMapFloatOOBfill);

static CUresult encode_map(PFN_encodeTiled enc, CUtensorMap* tm, void* ptr,
                           unsigned long long rows, unsigned box_rows) {
    cuuint64_t dims[2]    = {(cuuint64_t)HWX, (cuuint64_t)rows};
    cuuint64_t strides[1] = {(cuuint64_t)HWX};          // bytes (int8)
    cuuint32_t box[2]     = {BKS, box_rows};            // 128 x rows
    cuuint32_t estr[2]    = {1, 1};
    return enc(tm, CU_TENSOR_MAP_DATA_TYPE_UINT8, 2, ptr, dims, strides, box, estr,
               CU_TENSOR_MAP_INTERLEAVE_NONE, CU_TENSOR_MAP_SWIZZLE_128B,
               CU_TENSOR_MAP_L2_PROMOTION_L2_128B, CU_TENSOR_MAP_FLOAT_OOB_FILL_NONE);
}

extern "C" void kernel_launch(void* const* d_in, const int* in_sizes, int n_in,
                              void* d_out, int out_size) {
    const float* pred_logits = (const float*)d_in[0];
    const float* pred_boxes  = (const float*)d_in[1];
    const float* pred_masks  = (const float*)d_in[2];
    const float* tgt_boxes   = (const float*)d_in[3];
    const float* tgt_masks   = (const float*)d_in[4];
    const void*  tgt_labels  = (const void*)d_in[5];
    float* out = (float*)d_out;

    aux_kernel<<<PP + TT + 1, 256>>>(pred_logits, pred_masks, tgt_masks, tgt_labels);

    // Try the TMA path; verified fallback to cp.async path.
    bool tma_ok = false;
    alignas(64) CUtensorMap tmA1, tmA2, tmB;
    void* fp = nullptr;
#if CUDART_VERSION >= 12000
    cudaDriverEntryPointQueryResult qr;
    cudaError_t e0 = cudaGetDriverEntryPoint("cuTensorMapEncodeTiled", &fp,
                                             cudaEnableDefault, &qr);
#else
    cudaError_t e0 = cudaGetDriverEntryPoint("cuTensorMapEncodeTiled", &fp,
                                             cudaEnableDefault);
#endif
    if (e0 == cudaSuccess && fp != nullptr) {
        PFN_encodeTiled enc = (PFN_encodeTiled)fp;
        void *pa1 = nullptr, *pa2 = nullptr, *pb = nullptr;
        cudaError_t s1 = cudaGetSymbolAddress(&pa1, g_A1q);
        cudaError_t s2 = cudaGetSymbolAddress(&pa2, g_A2q);
        cudaError_t s3 = cudaGetSymbolAddress(&pb,  g_tmq);
        if (s1 == cudaSuccess && s2 == cudaSuccess && s3 == cudaSuccess) {
            CUresult r1 = encode_map(enc, &tmA1, pa1, PP, BM_T);
            CUresult r2 = encode_map(enc, &tmA2, pa2, PP, BM_T);
            CUresult r3 = encode_map(enc, &tmB,  pb,  TT, BN_T);
            tma_ok = (r1 == CUDA_SUCCESS && r2 == CUDA_SUCCESS && r3 == CUDA_SUCCESS);
        }
    }

    dim3 grid((TT + BN_T - 1) / BN_T, (PP + BM_T - 1) / BM_T);   // 3 x 43 = 129
    if (tma_ok) {
        cudaFuncSetAttribute(gemm_tma, cudaFuncAttributeMaxDynamicSharedMemorySize, DYN_SMEM);
        gemm_tma<<<grid, NT_TMA, DYN_SMEM>>>(tmA1, tmA2, tmB, pred_boxes, tgt_boxes, out);
    } else {
        cudaFuncSetAttribute(gemm_cpasync, cudaFuncAttributeMaxDynamicSharedMemorySize, DYN_SMEM);
        gemm_cpasync<<<grid, NT_TMA, DYN_SMEM>>>(pred_boxes, tgt_boxes, out);
    }
}